// round 4
// baseline (speedup 1.0000x reference)
#include <cuda_runtime.h>

#define NB 128
#define NL 36
#define NV 36
#define ND 512
#define NKV 112
#define NQ 36
#define NH 512
#define G3 108
#define CKDIM 812   // D + KD
#define XDIM 624    // D + KV

typedef unsigned long long u64;

__device__ __forceinline__ void ffma2(u64& d, u64 a, u64 b) {
    asm("fma.rn.f32x2 %0, %1, %2, %0;" : "+l"(d) : "l"(a), "l"(b));
}
__device__ __forceinline__ float hsum2(u64 v) {
    float lo, hi;
    asm("mov.b64 {%0,%1}, %2;" : "=f"(lo), "=f"(hi) : "l"(v));
    return lo + hi;
}

// ---------------- scratch (device globals; no allocs allowed) ----------------
__device__ float g_csumWT[NB * G3 * NQ];  // [b][o][v]: ((sum_l ctx) @ Wih_u^T)^T
__device__ float g_gk[NB * NL * G3];      // knowledge @ Wih_k^T + bih
__device__ float g_w[NB * ND];            // per-iteration projection vector
__device__ float g_WihuO[G3 * ND];        // Wih rows, first 512 cols (row-major copy)
__device__ float g_WihkT[NKV * G3];       // transposed knowledge part

// ---------------- weight prep ----------------
__global__ void k_prep(const float* __restrict__ Wih) {
    int i = blockIdx.x * blockDim.x + threadIdx.x;
    if (i < G3 * ND)  { int o = i / ND, c = i % ND; g_WihuO[i] = Wih[o * XDIM + c]; }
    if (i < NKV * G3) { int c = i / G3, o = i % G3; g_WihkT[i] = Wih[o * XDIM + ND + c]; }
}

// ---------------- gk = knowledge @ Wih_k^T + bih (iteration-invariant) ----------------
__global__ void k_gk(const float* __restrict__ kn, const float* __restrict__ bih) {
    __shared__ float knS[NKV];
    int row = blockIdx.x;            // b*36 + l
    int t = threadIdx.x;
    if (t < NKV) knS[t] = kn[row * NKV + t];
    __syncthreads();
    if (t < G3) {
        float acc = bih[t];
        #pragma unroll 4
        for (int c = 0; c < NKV; c++) acc += knS[c] * g_WihkT[c * G3 + t];
        g_gk[row * G3 + t] = acc;
    }
}

// ---------------- per-iteration projection vector w[b, 0:512] ----------------
__global__ void k_w(const float* __restrict__ slots, int bstride,
                    const float* __restrict__ lng, const float* __restrict__ lnb,
                    const float* __restrict__ Wq, const float* __restrict__ Wk) {
    int b = blockIdx.x;
    int t = threadIdx.x, lane = t & 31, wid = t >> 5;
    __shared__ float lnS[NQ * NQ];
    __shared__ float lnsum[NQ];
    __shared__ float qsum[NQ];
    const float* sp = slots + (size_t)bstride * b;
    for (int i = wid; i < NQ; i += 8) {
        float v1 = (lane < NQ)      ? sp[i * NQ + lane]      : 0.f;
        float v2 = (lane < NQ - 32) ? sp[i * NQ + lane + 32] : 0.f;
        float s = v1 + v2;
        for (int o = 16; o; o >>= 1) s += __shfl_xor_sync(~0u, s, o);
        float mu = s * (1.f / 36.f);
        float d1 = (lane < NQ) ? (v1 - mu) : 0.f;
        float d2 = (lane < NQ - 32) ? (v2 - mu) : 0.f;
        float vv = d1 * d1 + d2 * d2;
        for (int o = 16; o; o >>= 1) vv += __shfl_xor_sync(~0u, vv, o);
        float inv = rsqrtf(vv * (1.f / 36.f) + 1e-5f);
        if (lane < NQ)      lnS[i * NQ + lane]      = d1 * inv * lng[lane] + lnb[lane];
        if (lane < NQ - 32) lnS[i * NQ + lane + 32] = d2 * inv * lng[lane + 32] + lnb[lane + 32];
    }
    __syncthreads();
    if (t < NQ) {
        float s = 0.f;
        for (int i = 0; i < NQ; i++) s += lnS[i * NQ + t];
        lnsum[t] = s;
    }
    __syncthreads();
    if (t < NQ) {
        float s = 0.f;
        #pragma unroll 4
        for (int e = 0; e < NQ; e++) s += lnsum[e] * Wq[t * NQ + e];
        qsum[t] = s;
    }
    __syncthreads();
    for (int c = t; c < ND; c += blockDim.x) {
        float s = 0.f;
        #pragma unroll 4
        for (int d = 0; d < NQ; d++) s += qsum[d] * Wk[d * CKDIM + c];
        g_w[b * ND + c] = s * (1.f / 6.f);   // scale = 36^-0.5 folded in
    }
}

// ---------------- pass 1 over context: dots(iter0) + csumW^T ----------------
// block (v, b), 9 warps; warp w owns l in [4w, 4w+4). No syncs in mainloop;
// bounded MLP (16 LDG.128/lane); cross-warp csum reduced via smem at the end.
__global__ __launch_bounds__(288) void k_c(const float* __restrict__ ctx,
                                           float* __restrict__ dots0) {
    int v = blockIdx.x, b = blockIdx.y;
    int t = threadIdx.x, lane = t & 31, w = t >> 5;
    __shared__ float csumP[9 * ND];   // per-warp csum partials
    __shared__ float csumS[ND];
    __shared__ float dotsS[NL];
    const float4* wb = (const float4*)(g_w + b * ND);
    float4 w0 = wb[lane], w1 = wb[lane + 32], w2 = wb[lane + 64], w3 = wb[lane + 96];
    float4 a0 = {0,0,0,0}, a1 = {0,0,0,0}, a2 = {0,0,0,0}, a3 = {0,0,0,0};
    float pp[4];
    const float4* base = (const float4*)ctx + ((size_t)b * NL * NV + v) * (ND / 4);
    #pragma unroll
    for (int li = 0; li < 4; li++) {
        int l = w * 4 + li;
        const float4* p = base + (size_t)l * NV * (ND / 4);
        float4 c0 = p[lane], c1 = p[lane + 32], c2 = p[lane + 64], c3 = p[lane + 96];
        a0.x += c0.x; a0.y += c0.y; a0.z += c0.z; a0.w += c0.w;
        a1.x += c1.x; a1.y += c1.y; a1.z += c1.z; a1.w += c1.w;
        a2.x += c2.x; a2.y += c2.y; a2.z += c2.z; a2.w += c2.w;
        a3.x += c3.x; a3.y += c3.y; a3.z += c3.z; a3.w += c3.w;
        pp[li] = c0.x * w0.x + c0.y * w0.y + c0.z * w0.z + c0.w * w0.w
               + c1.x * w1.x + c1.y * w1.y + c1.z * w1.z + c1.w * w1.w
               + c2.x * w2.x + c2.y * w2.y + c2.z * w2.z + c2.w * w2.w
               + c3.x * w3.x + c3.y * w3.y + c3.z * w3.z + c3.w * w3.w;
    }
    #pragma unroll
    for (int li = 0; li < 4; li++) {
        float r = pp[li];
        for (int o = 16; o; o >>= 1) r += __shfl_xor_sync(~0u, r, o);
        if (lane == 0) dotsS[w * 4 + li] = r;
    }
    float4* cp = (float4*)csumP + w * (ND / 4);
    cp[lane] = a0; cp[lane + 32] = a1; cp[lane + 64] = a2; cp[lane + 96] = a3;
    __syncthreads();
    if (t < ND / 4) {
        float4 s = ((float4*)csumP)[t];
        #pragma unroll
        for (int ww = 1; ww < 9; ww++) {
            float4 u = ((float4*)csumP)[ww * (ND / 4) + t];
            s.x += u.x; s.y += u.y; s.z += u.z; s.w += u.w;
        }
        ((float4*)csumS)[t] = s;
    }
    if (t >= 128 && t < 128 + NL)
        dots0[(b * NL + (t - 128)) * NV + v] = dotsS[t - 128];
    __syncthreads();
    if (t < G3) {
        int o = t;
        u64 s0 = 0, s1 = 0;
        const ulonglong2* cs = (const ulonglong2*)csumS;
        const ulonglong2* wr = (const ulonglong2*)(g_WihuO + o * ND);
        #pragma unroll 16
        for (int c = 0; c < ND / 4; c++) {
            ulonglong2 u = cs[c];
            ulonglong2 ww = wr[c];
            ffma2(s0, u.x, ww.x);
            ffma2(s1, u.y, ww.y);
        }
        g_csumWT[b * G3 * NQ + o * NQ + v] = hsum2(s0) + hsum2(s1);
    }
}

// ---------------- in-place softmax over views (iter0) ----------------
__global__ void k_sm(float* __restrict__ a) {
    int row = blockIdx.x;
    int lane = threadIdx.x;
    float x1 = a[row * NV + lane];
    float x2 = (lane + 32 < NV) ? a[row * NV + lane + 32] : -1e30f;
    float m = fmaxf(x1, x2);
    for (int o = 16; o; o >>= 1) m = fmaxf(m, __shfl_xor_sync(~0u, m, o));
    float e1 = expf(x1 - m);
    float e2 = (lane + 32 < NV) ? expf(x2 - m) : 0.f;
    float s = e1 + e2;
    for (int o = 16; o; o >>= 1) s += __shfl_xor_sync(~0u, s, o);
    float inv = 1.f / s;
    a[row * NV + lane] = e1 * inv;
    if (lane + 32 < NV) a[row * NV + lane + 32] = e2 * inv;
}

// ---------------- iters 1,2: streaming dots + fused softmax ----------------
__global__ __launch_bounds__(256) void k_d(const float* __restrict__ ctx,
                                           float* __restrict__ attnT) {
    int tile = blockIdx.x, b = blockIdx.y;       // tile 0..17
    int t = threadIdx.x, lane = t & 31, w = t >> 5;
    __shared__ float dotsS[72];
    const float4* wb = (const float4*)(g_w + b * ND);
    float4 w0 = wb[lane], w1 = wb[lane + 32], w2 = wb[lane + 64], w3 = wb[lane + 96];
    int row0 = tile * 72 + w * 9;
    const float4* base = (const float4*)ctx + ((size_t)b * (NL * NV) + row0) * (ND / 4);
    float pp[9];
    #pragma unroll
    for (int r = 0; r < 9; r++) {
        const float4* p = base + r * (ND / 4);
        float4 c0 = p[lane], c1 = p[lane + 32], c2 = p[lane + 64], c3 = p[lane + 96];
        pp[r] = c0.x * w0.x + c0.y * w0.y + c0.z * w0.z + c0.w * w0.w
              + c1.x * w1.x + c1.y * w1.y + c1.z * w1.z + c1.w * w1.w
              + c2.x * w2.x + c2.y * w2.y + c2.z * w2.z + c2.w * w2.w
              + c3.x * w3.x + c3.y * w3.y + c3.z * w3.z + c3.w * w3.w;
    }
    #pragma unroll
    for (int r = 0; r < 9; r++) {
        float v = pp[r];
        for (int o = 16; o; o >>= 1) v += __shfl_xor_sync(~0u, v, o);
        if (lane == 0) dotsS[w * 9 + r] = v;
    }
    __syncthreads();
    if (w < 2) {
        float x1 = dotsS[w * 36 + lane];
        float x2 = (lane < 4) ? dotsS[w * 36 + lane + 32] : -1e30f;
        float m = fmaxf(x1, x2);
        for (int o = 16; o; o >>= 1) m = fmaxf(m, __shfl_xor_sync(~0u, m, o));
        float e1 = expf(x1 - m);
        float e2 = (lane < 4) ? expf(x2 - m) : 0.f;
        float s = e1 + e2;
        for (int o = 16; o; o >>= 1) s += __shfl_xor_sync(~0u, s, o);
        float inv = 1.f / s;
        int l = tile * 2 + w;
        float* arow = attnT + (b * NL + l) * NV;
        arow[lane] = e1 * inv;
        if (lane < 4) arow[lane + 32] = e2 * inv;
    }
}

// ---------------- fused GRU + LN + MLP per batch element (f32x2 + LDS.128) ----------------
__global__ __launch_bounds__(512) void k_g(const float* __restrict__ attnT,
                                           const float* __restrict__ slots_prev, int bstride,
                                           const float* __restrict__ Whh,
                                           const float* __restrict__ bhh,
                                           const float* __restrict__ lnfg, const float* __restrict__ lnfb,
                                           const float* __restrict__ W1, const float* __restrict__ b1,
                                           const float* __restrict__ W2, const float* __restrict__ b2,
                                           float* __restrict__ slots_out) {
    extern __shared__ float sm[];
    float* attnS = sm;              // 1296
    float* hpS   = attnS + 1296;    // 1296
    float* gxS   = hpS + 1296;      // 3888
    float* ghS   = gxS + 3888;      // 3888
    float* gnewS = ghS + 3888;      // 1296
    float* ffS   = gnewS + 1296;    // 1296
    float* hidS  = ffS + 1296;      // 36*512
    float* W2S   = hidS + NQ * NH;  // 36*516
    int b = blockIdx.x;
    int t = threadIdx.x, lane = t & 31, wp = t >> 5;

    for (int i = t; i < 1296; i += 512) {
        attnS[i] = attnT[b * 1296 + i];
        hpS[i] = slots_prev[(size_t)bstride * b + i];
    }
    for (int i = t; i < NQ * NH; i += 512) {
        int q = i >> 9, c = i & 511;
        W2S[q * 516 + c] = W2[i];
    }
    __syncthreads();

    for (int idx = t; idx < NQ * G3; idx += 512) {
        int i = idx / G3, o = idx - i * G3;
        u64 a0 = 0, a1 = 0;
        const ulonglong2* ar = (const ulonglong2*)(attnS + i * NQ);
        const ulonglong2* cw = (const ulonglong2*)(g_csumWT + b * G3 * NQ + o * NQ);
        #pragma unroll
        for (int c = 0; c < 9; c++) {
            ulonglong2 u = ar[c], v = cw[c];
            ffma2(a0, u.x, v.x);
            ffma2(a1, u.y, v.y);
        }
        gxS[idx] = g_gk[(b * NQ + i) * G3 + o] + hsum2(a0) + hsum2(a1);
        u64 h0 = 0, h1 = 0;
        const ulonglong2* hr = (const ulonglong2*)(hpS + i * NQ);
        const ulonglong2* wh = (const ulonglong2*)(Whh + o * NQ);
        #pragma unroll
        for (int c = 0; c < 9; c++) {
            ulonglong2 u = hr[c], v = wh[c];
            ffma2(h0, u.x, v.x);
            ffma2(h1, u.y, v.y);
        }
        ghS[idx] = bhh[o] + hsum2(h0) + hsum2(h1);
    }
    __syncthreads();

    for (int idx = t; idx < 1296; idx += 512) {
        int i = idx / NQ, qq = idx - i * NQ;
        float r = 1.f / (1.f + expf(-(gxS[i * G3 + qq] + ghS[i * G3 + qq])));
        float z = 1.f / (1.f + expf(-(gxS[i * G3 + NQ + qq] + ghS[i * G3 + NQ + qq])));
        float n = tanhf(gxS[i * G3 + 2 * NQ + qq] + r * ghS[i * G3 + 2 * NQ + qq]);
        gnewS[idx] = (1.f - z) * n + z * hpS[idx];
    }
    __syncthreads();

    for (int i = wp; i < NQ; i += 16) {
        float v1 = (lane < NQ) ? gnewS[i * NQ + lane] : 0.f;
        float v2 = (lane < 4)  ? gnewS[i * NQ + lane + 32] : 0.f;
        float s = v1 + v2;
        for (int o = 16; o; o >>= 1) s += __shfl_xor_sync(~0u, s, o);
        float mu = s * (1.f / 36.f);
        float d1 = (lane < NQ) ? (v1 - mu) : 0.f;
        float d2 = (lane < 4)  ? (v2 - mu) : 0.f;
        float vv = d1 * d1 + d2 * d2;
        for (int o = 16; o; o >>= 1) vv += __shfl_xor_sync(~0u, vv, o);
        float inv = rsqrtf(vv * (1.f / 36.f) + 1e-5f);
        if (lane < NQ) ffS[i * NQ + lane]      = d1 * inv * lnfg[lane] + lnfb[lane];
        if (lane < 4)  ffS[i * NQ + lane + 32] = d2 * inv * lnfg[lane + 32] + lnfb[lane + 32];
    }
    __syncthreads();

    {
        int h = t;
        ulonglong2 w1p[9];
        const ulonglong2* wr = (const ulonglong2*)(W1 + h * NQ);
        #pragma unroll
        for (int c = 0; c < 9; c++) w1p[c] = wr[c];
        float bb = b1[h];
        for (int i = 0; i < NQ; i++) {
            u64 a0 = 0, a1 = 0;
            const ulonglong2* fr = (const ulonglong2*)(ffS + i * NQ);
            #pragma unroll
            for (int c = 0; c < 9; c++) {
                ulonglong2 u = fr[c];
                ffma2(a0, u.x, w1p[c].x);
                ffma2(a1, u.y, w1p[c].y);
            }
            hidS[i * NH + h] = fmaxf(bb + hsum2(a0) + hsum2(a1), 0.f);
        }
    }
    __syncthreads();

    for (int idx = t; idx < 1296; idx += 512) {
        int i = idx / NQ, qq = idx - i * NQ;
        u64 a0 = 0, a1 = 0;
        const ulonglong2* hr = (const ulonglong2*)(hidS + i * NH);
        const ulonglong2* wr = (const ulonglong2*)(W2S + qq * 516);
        #pragma unroll 8
        for (int c = 0; c < NH / 4; c++) {
            ulonglong2 u = hr[c], v = wr[c];
            ffma2(a0, u.x, v.x);
            ffma2(a1, u.y, v.y);
        }
        slots_out[b * 1296 + idx] = gnewS[idx] + b2[qq] + hsum2(a0) + hsum2(a1);
    }
}

static const int KG_SMEM = (1296 + 1296 + 3888 + 3888 + 1296 + 1296 + NQ * NH + NQ * 516) * 4;

extern "C" void kernel_launch(void* const* d_in, const int* in_sizes, int n_in,
                              void* d_out, int out_size) {
    const float* ctx  = (const float*)d_in[1];
    const float* kn   = (const float*)d_in[4];
    const float* pano = (const float*)d_in[5];
    const float* Wq   = (const float*)d_in[6];
    const float* Wk   = (const float*)d_in[7];
    const float* Wih  = (const float*)d_in[8];
    const float* Whh  = (const float*)d_in[9];
    const float* bih  = (const float*)d_in[10];
    const float* bhh  = (const float*)d_in[11];
    const float* lsg  = (const float*)d_in[12];
    const float* lsb  = (const float*)d_in[13];
    const float* lfg  = (const float*)d_in[14];
    const float* lfb  = (const float*)d_in[15];
    const float* W1   = (const float*)d_in[16];
    const float* b1   = (const float*)d_in[17];
    const float* W2   = (const float*)d_in[18];
    const float* b2   = (const float*)d_in[19];

    float* out = (float*)d_out;
    float* slots = out;                       // [B,36,36]
    // attn slabs: [3,B,36,36] right after slots

    cudaFuncSetAttribute(k_g, cudaFuncAttributeMaxDynamicSharedMemorySize, KG_SMEM);

    k_prep<<<(G3 * ND + 255) / 256, 256>>>(Wih);
    k_gk<<<NB * NL, 128>>>(kn, bih);

    for (int it = 0; it < 3; it++) {
        float* attnT = out + NB * NL * NV * (1 + it);
        const float* sp = it ? (const float*)slots : pano;
        int bs = it ? 1296 : 0;
        k_w<<<NB, 256>>>(sp, bs, lsg, lsb, Wq, Wk);
        if (it == 0) {
            k_c<<<dim3(NV, NB), 288>>>(ctx, attnT);
            k_sm<<<NB * NL, 32>>>(attnT);
        } else {
            k_d<<<dim3(18, NB), 256>>>(ctx, attnT);
        }
        k_g<<<NB, 512, KG_SMEM>>>(attnT, sp, bs, Whh, bhh, lfg, lfb, W1, b1, W2, b2, slots);
    }
}

// round 5
// speedup vs baseline: 1.3033x; 1.3033x over previous
#include <cuda_runtime.h>

#define NB 128
#define NL 36
#define NV 36
#define ND 512
#define NKV 112
#define NQ 36
#define NH 512
#define G3 108
#define CKDIM 812   // D + KD
#define XDIM 624    // D + KV

typedef unsigned long long u64;

__device__ __forceinline__ void ffma2(u64& d, u64 a, u64 b) {
    asm("fma.rn.f32x2 %0, %1, %2, %0;" : "+l"(d) : "l"(a), "l"(b));
}
__device__ __forceinline__ float hsum2(u64 v) {
    float lo, hi;
    asm("mov.b64 {%0,%1}, %2;" : "=f"(lo), "=f"(hi) : "l"(v));
    return lo + hi;
}

// ---------------- scratch ----------------
__device__ float g_csum[NB * NV * ND];    // per (b,v) sum over l of context
__device__ float g_csumWT[NB * G3 * NQ];  // [b][o][v]
__device__ float g_gk[NB * NL * G3];      // knowledge @ Wih_k^T + bih
__device__ float g_w[NB * ND];            // per-iteration projection vector
__device__ float g_WihuO[G3 * ND];        // Wih rows, first 512 cols
__device__ float g_WihkT[NKV * G3];       // transposed knowledge part

// ---------------- weight prep ----------------
__global__ void k_prep(const float* __restrict__ Wih) {
    int i = blockIdx.x * blockDim.x + threadIdx.x;
    if (i < G3 * ND)  { int o = i / ND, c = i % ND; g_WihuO[i] = Wih[o * XDIM + c]; }
    if (i < NKV * G3) { int c = i / G3, o = i % G3; g_WihkT[i] = Wih[o * XDIM + ND + c]; }
}

// ---------------- gk = knowledge @ Wih_k^T + bih ----------------
__global__ void k_gk(const float* __restrict__ kn, const float* __restrict__ bih) {
    __shared__ float knS[NKV];
    int row = blockIdx.x;
    int t = threadIdx.x;
    if (t < NKV) knS[t] = kn[row * NKV + t];
    __syncthreads();
    if (t < G3) {
        float acc = bih[t];
        #pragma unroll 4
        for (int c = 0; c < NKV; c++) acc += knS[c] * g_WihkT[c * G3 + t];
        g_gk[row * G3 + t] = acc;
    }
}

// ---------------- iter-0 projection vector (from pano) ----------------
__global__ void k_w(const float* __restrict__ slots, int bstride,
                    const float* __restrict__ lng, const float* __restrict__ lnb,
                    const float* __restrict__ Wq, const float* __restrict__ Wk) {
    int b = blockIdx.x;
    int t = threadIdx.x, lane = t & 31, wid = t >> 5;
    __shared__ float lnS[NQ * NQ];
    __shared__ float lnsum[NQ];
    __shared__ float qsum[NQ];
    const float* sp = slots + (size_t)bstride * b;
    for (int i = wid; i < NQ; i += 8) {
        float v1 = (lane < NQ)      ? sp[i * NQ + lane]      : 0.f;
        float v2 = (lane < NQ - 32) ? sp[i * NQ + lane + 32] : 0.f;
        float s = v1 + v2;
        for (int o = 16; o; o >>= 1) s += __shfl_xor_sync(~0u, s, o);
        float mu = s * (1.f / 36.f);
        float d1 = (lane < NQ) ? (v1 - mu) : 0.f;
        float d2 = (lane < NQ - 32) ? (v2 - mu) : 0.f;
        float vv = d1 * d1 + d2 * d2;
        for (int o = 16; o; o >>= 1) vv += __shfl_xor_sync(~0u, vv, o);
        float inv = rsqrtf(vv * (1.f / 36.f) + 1e-5f);
        if (lane < NQ)      lnS[i * NQ + lane]      = d1 * inv * lng[lane] + lnb[lane];
        if (lane < NQ - 32) lnS[i * NQ + lane + 32] = d2 * inv * lng[lane + 32] + lnb[lane + 32];
    }
    __syncthreads();
    if (t < NQ) {
        float s = 0.f;
        for (int i = 0; i < NQ; i++) s += lnS[i * NQ + t];
        lnsum[t] = s;
    }
    __syncthreads();
    if (t < NQ) {
        float s = 0.f;
        #pragma unroll 4
        for (int e = 0; e < NQ; e++) s += lnsum[e] * Wq[t * NQ + e];
        qsum[t] = s;
    }
    __syncthreads();
    for (int c = t; c < ND; c += blockDim.x) {
        float s = 0.f;
        #pragma unroll 4
        for (int d = 0; d < NQ; d++) s += qsum[d] * Wk[d * CKDIM + c];
        g_w[b * ND + c] = s * (1.f / 6.f);
    }
}

// ---------------- pure streaming sum over l: minimal regs, max occupancy ----------------
__global__ __launch_bounds__(128) void k_csum(const float* __restrict__ ctx) {
    int v = blockIdx.x, b = blockIdx.y;
    int t = threadIdx.x;
    const float4* base = (const float4*)ctx + ((size_t)b * NL * NV + v) * (ND / 4) + t;
    float4 acc = {0.f, 0.f, 0.f, 0.f};
    #pragma unroll 4
    for (int l = 0; l < NL; l++) {
        float4 c = base[(size_t)l * NV * (ND / 4)];
        acc.x += c.x; acc.y += c.y; acc.z += c.z; acc.w += c.w;
    }
    ((float4*)g_csum)[(b * NV + v) * (ND / 4) + t] = acc;
}

// ---------------- projection: csumWT[b] = Wihu @ csum[b]^T (one block per b) ----------------
__global__ __launch_bounds__(512) void k_projW() {
    int b = blockIdx.x;
    int t = threadIdx.x, lane = t & 31, w = t >> 5;  // 16 warps
    extern __shared__ float cs[];                    // 36*512 floats
    const float4* src = (const float4*)(g_csum + (size_t)b * NV * ND);
    for (int i = t; i < NV * ND / 4; i += 512) ((float4*)cs)[i] = src[i];
    __syncthreads();
    for (int o = w; o < G3; o += 16) {
        float4 wv0, wv1, wv2, wv3;
        const float4* wr = (const float4*)(g_WihuO + o * ND);
        wv0 = wr[lane]; wv1 = wr[lane + 32]; wv2 = wr[lane + 64]; wv3 = wr[lane + 96];
        for (int v = 0; v < NV; v++) {
            const float4* cv = (const float4*)(cs + v * ND);
            float4 u0 = cv[lane], u1 = cv[lane + 32], u2 = cv[lane + 64], u3 = cv[lane + 96];
            float p = u0.x * wv0.x + u0.y * wv0.y + u0.z * wv0.z + u0.w * wv0.w
                    + u1.x * wv1.x + u1.y * wv1.y + u1.z * wv1.z + u1.w * wv1.w
                    + u2.x * wv2.x + u2.y * wv2.y + u2.z * wv2.z + u2.w * wv2.w
                    + u3.x * wv3.x + u3.y * wv3.y + u3.z * wv3.z + u3.w * wv3.w;
            for (int of = 16; of; of >>= 1) p += __shfl_xor_sync(~0u, p, of);
            if (lane == 0) g_csumWT[b * G3 * NQ + o * NQ + v] = p;
        }
    }
}

// ---------------- dots + fused softmax (all 3 iterations) ----------------
__global__ __launch_bounds__(256) void k_d(const float* __restrict__ ctx,
                                           float* __restrict__ attnT) {
    int tile = blockIdx.x, b = blockIdx.y;
    int t = threadIdx.x, lane = t & 31, w = t >> 5;
    __shared__ float dotsS[72];
    const float4* wb = (const float4*)(g_w + b * ND);
    float4 w0 = wb[lane], w1 = wb[lane + 32], w2 = wb[lane + 64], w3 = wb[lane + 96];
    int row0 = tile * 72 + w * 9;
    const float4* base = (const float4*)ctx + ((size_t)b * (NL * NV) + row0) * (ND / 4);
    float pp[9];
    #pragma unroll
    for (int r = 0; r < 9; r++) {
        const float4* p = base + r * (ND / 4);
        float4 c0 = p[lane], c1 = p[lane + 32], c2 = p[lane + 64], c3 = p[lane + 96];
        pp[r] = c0.x * w0.x + c0.y * w0.y + c0.z * w0.z + c0.w * w0.w
              + c1.x * w1.x + c1.y * w1.y + c1.z * w1.z + c1.w * w1.w
              + c2.x * w2.x + c2.y * w2.y + c2.z * w2.z + c2.w * w2.w
              + c3.x * w3.x + c3.y * w3.y + c3.z * w3.z + c3.w * w3.w;
    }
    #pragma unroll
    for (int r = 0; r < 9; r++) {
        float v = pp[r];
        for (int o = 16; o; o >>= 1) v += __shfl_xor_sync(~0u, v, o);
        if (lane == 0) dotsS[w * 9 + r] = v;
    }
    __syncthreads();
    if (w < 2) {
        float x1 = dotsS[w * 36 + lane];
        float x2 = (lane < 4) ? dotsS[w * 36 + lane + 32] : -1e30f;
        float m = fmaxf(x1, x2);
        for (int o = 16; o; o >>= 1) m = fmaxf(m, __shfl_xor_sync(~0u, m, o));
        float e1 = expf(x1 - m);
        float e2 = (lane < 4) ? expf(x2 - m) : 0.f;
        float s = e1 + e2;
        for (int o = 16; o; o >>= 1) s += __shfl_xor_sync(~0u, s, o);
        float inv = 1.f / s;
        int l = tile * 2 + w;
        float* arow = attnT + (b * NL + l) * NV;
        arow[lane] = e1 * inv;
        if (lane < 4) arow[lane + 32] = e2 * inv;
    }
}

// ---------------- fused GRU + LN + MLP (+ next-iteration w) per batch ----------------
__global__ __launch_bounds__(512) void k_g(const float* __restrict__ attnT,
                                           const float* __restrict__ slots_prev, int bstride,
                                           const float* __restrict__ Whh,
                                           const float* __restrict__ bhh,
                                           const float* __restrict__ lnfg, const float* __restrict__ lnfb,
                                           const float* __restrict__ W1, const float* __restrict__ b1,
                                           const float* __restrict__ W2, const float* __restrict__ b2,
                                           const float* __restrict__ lsg, const float* __restrict__ lsb,
                                           const float* __restrict__ Wq, const float* __restrict__ Wk,
                                           int do_w,
                                           float* __restrict__ slots_out) {
    extern __shared__ float sm[];
    float* attnS = sm;              // 1296
    float* hpS   = attnS + 1296;    // 1296
    float* gxS   = hpS + 1296;      // 3888 (reused as outS)
    float* ghS   = gxS + 3888;      // 3888 (reused as lnS/lnsum/qsum)
    float* gnewS = ghS + 3888;      // 1296
    float* ffS   = gnewS + 1296;    // 1296
    float* hidS  = ffS + 1296;      // 36*512
    float* W2S   = hidS + NQ * NH;  // 36*516
    float* outS  = gxS;
    float* lnS   = ghS;
    float* lnsum = ghS + 1296;
    float* qsum  = ghS + 1296 + 64;
    int b = blockIdx.x;
    int t = threadIdx.x, lane = t & 31, wp = t >> 5;

    for (int i = t; i < 1296; i += 512) {
        attnS[i] = attnT[b * 1296 + i];
        hpS[i] = slots_prev[(size_t)bstride * b + i];
    }
    for (int i = t; i < NQ * NH; i += 512) {
        int q = i >> 9, c = i & 511;
        W2S[q * 516 + c] = W2[i];
    }
    __syncthreads();

    for (int idx = t; idx < NQ * G3; idx += 512) {
        int i = idx / G3, o = idx - i * G3;
        u64 a0 = 0, a1 = 0;
        const ulonglong2* ar = (const ulonglong2*)(attnS + i * NQ);
        const ulonglong2* cw = (const ulonglong2*)(g_csumWT + b * G3 * NQ + o * NQ);
        #pragma unroll
        for (int c = 0; c < 9; c++) {
            ulonglong2 u = ar[c], v = cw[c];
            ffma2(a0, u.x, v.x);
            ffma2(a1, u.y, v.y);
        }
        gxS[idx] = g_gk[(b * NQ + i) * G3 + o] + hsum2(a0) + hsum2(a1);
        u64 h0 = 0, h1 = 0;
        const ulonglong2* hr = (const ulonglong2*)(hpS + i * NQ);
        const ulonglong2* wh = (const ulonglong2*)(Whh + o * NQ);
        #pragma unroll
        for (int c = 0; c < 9; c++) {
            ulonglong2 u = hr[c], v = wh[c];
            ffma2(h0, u.x, v.x);
            ffma2(h1, u.y, v.y);
        }
        ghS[idx] = bhh[o] + hsum2(h0) + hsum2(h1);
    }
    __syncthreads();

    for (int idx = t; idx < 1296; idx += 512) {
        int i = idx / NQ, qq = idx - i * NQ;
        float r = 1.f / (1.f + expf(-(gxS[i * G3 + qq] + ghS[i * G3 + qq])));
        float z = 1.f / (1.f + expf(-(gxS[i * G3 + NQ + qq] + ghS[i * G3 + NQ + qq])));
        float n = tanhf(gxS[i * G3 + 2 * NQ + qq] + r * ghS[i * G3 + 2 * NQ + qq]);
        gnewS[idx] = (1.f - z) * n + z * hpS[idx];
    }
    __syncthreads();

    for (int i = wp; i < NQ; i += 16) {
        float v1 = (lane < NQ) ? gnewS[i * NQ + lane] : 0.f;
        float v2 = (lane < 4)  ? gnewS[i * NQ + lane + 32] : 0.f;
        float s = v1 + v2;
        for (int o = 16; o; o >>= 1) s += __shfl_xor_sync(~0u, s, o);
        float mu = s * (1.f / 36.f);
        float d1 = (lane < NQ) ? (v1 - mu) : 0.f;
        float d2 = (lane < 4)  ? (v2 - mu) : 0.f;
        float vv = d1 * d1 + d2 * d2;
        for (int o = 16; o; o >>= 1) vv += __shfl_xor_sync(~0u, vv, o);
        float inv = rsqrtf(vv * (1.f / 36.f) + 1e-5f);
        if (lane < NQ) ffS[i * NQ + lane]      = d1 * inv * lnfg[lane] + lnfb[lane];
        if (lane < 4)  ffS[i * NQ + lane + 32] = d2 * inv * lnfg[lane + 32] + lnfb[lane + 32];
    }
    __syncthreads();

    {
        int h = t;
        ulonglong2 w1p[9];
        const ulonglong2* wr = (const ulonglong2*)(W1 + h * NQ);
        #pragma unroll
        for (int c = 0; c < 9; c++) w1p[c] = wr[c];
        float bb = b1[h];
        for (int i = 0; i < NQ; i++) {
            u64 a0 = 0, a1 = 0;
            const ulonglong2* fr = (const ulonglong2*)(ffS + i * NQ);
            #pragma unroll
            for (int c = 0; c < 9; c++) {
                ulonglong2 u = fr[c];
                ffma2(a0, u.x, w1p[c].x);
                ffma2(a1, u.y, w1p[c].y);
            }
            hidS[i * NH + h] = fmaxf(bb + hsum2(a0) + hsum2(a1), 0.f);
        }
    }
    __syncthreads();

    for (int idx = t; idx < 1296; idx += 512) {
        int i = idx / NQ, qq = idx - i * NQ;
        u64 a0 = 0, a1 = 0;
        const ulonglong2* hr = (const ulonglong2*)(hidS + i * NH);
        const ulonglong2* wr = (const ulonglong2*)(W2S + qq * 516);
        #pragma unroll 8
        for (int c = 0; c < NH / 4; c++) {
            ulonglong2 u = hr[c], v = wr[c];
            ffma2(a0, u.x, v.x);
            ffma2(a1, u.y, v.y);
        }
        float val = gnewS[idx] + b2[qq] + hsum2(a0) + hsum2(a1);
        slots_out[b * 1296 + idx] = val;
        outS[idx] = val;
    }

    if (!do_w) return;
    __syncthreads();

    // ----- fused next-iteration w computation (LN_slots -> qsum -> Wk proj) -----
    for (int i = wp; i < NQ; i += 16) {
        float v1 = (lane < NQ) ? outS[i * NQ + lane] : 0.f;
        float v2 = (lane < 4)  ? outS[i * NQ + lane + 32] : 0.f;
        float s = v1 + v2;
        for (int o = 16; o; o >>= 1) s += __shfl_xor_sync(~0u, s, o);
        float mu = s * (1.f / 36.f);
        float d1 = (lane < NQ) ? (v1 - mu) : 0.f;
        float d2 = (lane < 4)  ? (v2 - mu) : 0.f;
        float vv = d1 * d1 + d2 * d2;
        for (int o = 16; o; o >>= 1) vv += __shfl_xor_sync(~0u, vv, o);
        float inv = rsqrtf(vv * (1.f / 36.f) + 1e-5f);
        if (lane < NQ) lnS[i * NQ + lane]      = d1 * inv * lsg[lane] + lsb[lane];
        if (lane < 4)  lnS[i * NQ + lane + 32] = d2 * inv * lsg[lane + 32] + lsb[lane + 32];
    }
    __syncthreads();
    if (t < NQ) {
        float s = 0.f;
        for (int i = 0; i < NQ; i++) s += lnS[i * NQ + t];
        lnsum[t] = s;
    }
    __syncthreads();
    if (t < NQ) {
        float s = 0.f;
        #pragma unroll 4
        for (int e = 0; e < NQ; e++) s += lnsum[e] * Wq[t * NQ + e];
        qsum[t] = s;
    }
    __syncthreads();
    {
        float s = 0.f;
        #pragma unroll 4
        for (int d = 0; d < NQ; d++) s += qsum[d] * Wk[d * CKDIM + t];
        g_w[b * ND + t] = s * (1.f / 6.f);
    }
}

static const int KG_SMEM = (1296 + 1296 + 3888 + 3888 + 1296 + 1296 + NQ * NH + NQ * 516) * 4;
static const int KP_SMEM = NV * ND * 4;

extern "C" void kernel_launch(void* const* d_in, const int* in_sizes, int n_in,
                              void* d_out, int out_size) {
    const float* ctx  = (const float*)d_in[1];
    const float* kn   = (const float*)d_in[4];
    const float* pano = (const float*)d_in[5];
    const float* Wq   = (const float*)d_in[6];
    const float* Wk   = (const float*)d_in[7];
    const float* Wih  = (const float*)d_in[8];
    const float* Whh  = (const float*)d_in[9];
    const float* bih  = (const float*)d_in[10];
    const float* bhh  = (const float*)d_in[11];
    const float* lsg  = (const float*)d_in[12];
    const float* lsb  = (const float*)d_in[13];
    const float* lfg  = (const float*)d_in[14];
    const float* lfb  = (const float*)d_in[15];
    const float* W1   = (const float*)d_in[16];
    const float* b1   = (const float*)d_in[17];
    const float* W2   = (const float*)d_in[18];
    const float* b2   = (const float*)d_in[19];

    float* out = (float*)d_out;
    float* slots = out;                       // [B,36,36]; attn slabs follow

    cudaFuncSetAttribute(k_g, cudaFuncAttributeMaxDynamicSharedMemorySize, KG_SMEM);
    cudaFuncSetAttribute(k_projW, cudaFuncAttributeMaxDynamicSharedMemorySize, KP_SMEM);

    k_prep<<<(G3 * ND + 255) / 256, 256>>>(Wih);
    k_gk<<<NB * NL, 128>>>(kn, bih);
    k_csum<<<dim3(NV, NB), 128>>>(ctx);
    k_projW<<<NB, 512, KP_SMEM>>>();
    k_w<<<NB, 256>>>(pano, 0, lsg, lsb, Wq, Wk);

    for (int it = 0; it < 3; it++) {
        float* attnT = out + NB * NL * NV * (1 + it);
        const float* sp = it ? (const float*)slots : pano;
        int bs = it ? 1296 : 0;
        k_d<<<dim3(18, NB), 256>>>(ctx, attnT);
        k_g<<<NB, 512, KG_SMEM>>>(attnT, sp, bs, Whh, bhh, lfg, lfb, W1, b1, W2, b2,
                                  lsg, lsb, Wq, Wk, it < 2 ? 1 : 0, slots);
    }
}

// round 6
// speedup vs baseline: 1.3448x; 1.0319x over previous
#include <cuda_runtime.h>

#define NB 128
#define NL 36
#define NV 36
#define ND 512
#define NKV 112
#define NQ 36
#define NH 512
#define G3 108
#define CKDIM 812   // D + KD
#define XDIM 624    // D + KV

typedef unsigned long long u64;

__device__ __forceinline__ void ffma2(u64& d, u64 a, u64 b) {
    asm("fma.rn.f32x2 %0, %1, %2, %0;" : "+l"(d) : "l"(a), "l"(b));
}
__device__ __forceinline__ float hsum2(u64 v) {
    float lo, hi;
    asm("mov.b64 {%0,%1}, %2;" : "=f"(lo), "=f"(hi) : "l"(v));
    return lo + hi;
}

// ---------------- scratch ----------------
__device__ float g_csum[NB * NV * ND];    // per (b,v) sum over l of context
__device__ float g_csumWT[NB * G3 * NQ];  // [b][o][v]
__device__ float g_gk[NB * NL * G3];      // knowledge @ Wih_k^T + bih
__device__ float g_w[NB * ND];            // per-iteration projection vector
__device__ float g_WihuO[G3 * ND];        // Wih rows, first 512 cols
__device__ float g_WihkT[NKV * G3];       // transposed knowledge part

// ---------------- weight prep ----------------
__global__ void k_prep(const float* __restrict__ Wih) {
    int i = blockIdx.x * blockDim.x + threadIdx.x;
    if (i < G3 * ND)  { int o = i / ND, c = i % ND; g_WihuO[i] = Wih[o * XDIM + c]; }
    if (i < NKV * G3) { int c = i / G3, o = i % G3; g_WihkT[i] = Wih[o * XDIM + ND + c]; }
}

// ---------------- gk = knowledge @ Wih_k^T + bih ----------------
__global__ void k_gk(const float* __restrict__ kn, const float* __restrict__ bih) {
    __shared__ float knS[NKV];
    int row = blockIdx.x;
    int t = threadIdx.x;
    if (t < NKV) knS[t] = kn[row * NKV + t];
    __syncthreads();
    if (t < G3) {
        float acc = bih[t];
        #pragma unroll 4
        for (int c = 0; c < NKV; c++) acc += knS[c] * g_WihkT[c * G3 + t];
        g_gk[row * G3 + t] = acc;
    }
}

// ---------------- iter-0 projection vector (from pano) ----------------
__global__ void k_w(const float* __restrict__ slots, int bstride,
                    const float* __restrict__ lng, const float* __restrict__ lnb,
                    const float* __restrict__ Wq, const float* __restrict__ Wk) {
    int b = blockIdx.x;
    int t = threadIdx.x, lane = t & 31, wid = t >> 5;
    __shared__ float lnS[NQ * NQ];
    __shared__ float lnsum[NQ];
    __shared__ float qsum[NQ];
    const float* sp = slots + (size_t)bstride * b;
    for (int i = wid; i < NQ; i += 8) {
        float v1 = (lane < NQ)      ? sp[i * NQ + lane]      : 0.f;
        float v2 = (lane < NQ - 32) ? sp[i * NQ + lane + 32] : 0.f;
        float s = v1 + v2;
        for (int o = 16; o; o >>= 1) s += __shfl_xor_sync(~0u, s, o);
        float mu = s * (1.f / 36.f);
        float d1 = (lane < NQ) ? (v1 - mu) : 0.f;
        float d2 = (lane < NQ - 32) ? (v2 - mu) : 0.f;
        float vv = d1 * d1 + d2 * d2;
        for (int o = 16; o; o >>= 1) vv += __shfl_xor_sync(~0u, vv, o);
        float inv = rsqrtf(vv * (1.f / 36.f) + 1e-5f);
        if (lane < NQ)      lnS[i * NQ + lane]      = d1 * inv * lng[lane] + lnb[lane];
        if (lane < NQ - 32) lnS[i * NQ + lane + 32] = d2 * inv * lng[lane + 32] + lnb[lane + 32];
    }
    __syncthreads();
    if (t < NQ) {
        float s = 0.f;
        for (int i = 0; i < NQ; i++) s += lnS[i * NQ + t];
        lnsum[t] = s;
    }
    __syncthreads();
    if (t < NQ) {
        float s = 0.f;
        #pragma unroll 4
        for (int e = 0; e < NQ; e++) s += lnsum[e] * Wq[t * NQ + e];
        qsum[t] = s;
    }
    __syncthreads();
    for (int c = t; c < ND; c += blockDim.x) {
        float s = 0.f;
        #pragma unroll 4
        for (int d = 0; d < NQ; d++) s += qsum[d] * Wk[d * CKDIM + c];
        g_w[b * ND + c] = s * (1.f / 6.f);
    }
}

// ---------------- fused iter-0: csum + dots in ONE context pass ----------------
// block (v, b), 128 threads. Mainloop: 1 LDG.128 + 4 FADD + 4 FFMA + 1 STS per l.
// No syncs/shuffles in loop; dots reduced once at the end by 4 warps.
__global__ __launch_bounds__(128) void k_cd(const float* __restrict__ ctx,
                                            float* __restrict__ dots0) {
    int v = blockIdx.x, b = blockIdx.y;
    int t = threadIdx.x, lane = t & 31, w = t >> 5;
    __shared__ float ppS[NL * 129];
    const float4* wb = (const float4*)(g_w + b * ND);
    float4 w4 = wb[t];
    float4 acc = {0.f, 0.f, 0.f, 0.f};
    const float4* base = (const float4*)ctx + ((size_t)b * NL * NV + v) * (ND / 4) + t;
    #pragma unroll 4
    for (int l = 0; l < NL; l++) {
        float4 c = base[(size_t)l * NV * (ND / 4)];
        acc.x += c.x; acc.y += c.y; acc.z += c.z; acc.w += c.w;
        ppS[l * 129 + t] = c.x * w4.x + c.y * w4.y + c.z * w4.z + c.w * w4.w;
    }
    ((float4*)g_csum)[(b * NV + v) * (ND / 4) + t] = acc;
    __syncthreads();
    for (int l = w; l < NL; l += 4) {
        float s = ppS[l * 129 + lane] + ppS[l * 129 + lane + 32]
                + ppS[l * 129 + lane + 64] + ppS[l * 129 + lane + 96];
        for (int o = 16; o; o >>= 1) s += __shfl_xor_sync(~0u, s, o);
        if (lane == 0) dots0[(b * NL + l) * NV + v] = s;
    }
}

// ---------------- projection: csumWT[b] = Wihu @ csum[b]^T ----------------
// grid (NB, 4): each block does 27 o's. csum staged pitch-516 (conflict-free
// LDS.128), Wihu tile staged in smem. Inner: 2 LDS.128 + 4 FFMA per 4 MACs.
__global__ __launch_bounds__(512) void k_projW() {
    int b = blockIdx.x, part = blockIdx.y;
    int t = threadIdx.x;
    extern __shared__ float sm[];
    float* csS = sm;                    // 36 rows, pitch 516
    float* wkS = sm + NV * 516;         // 27 rows, pitch 512
    const float4* src = (const float4*)(g_csum + (size_t)b * NV * ND);
    for (int i = t; i < NV * 128; i += 512) {
        int v = i >> 7, c4 = i & 127;
        ((float4*)(csS + v * 516))[c4] = src[i];
    }
    int o0 = part * 27;
    const float4* wsrc = (const float4*)(g_WihuO + o0 * ND);
    for (int i = t; i < 27 * 128; i += 512)
        ((float4*)wkS)[i] = wsrc[i];
    __syncthreads();
    for (int idx = t; idx < 27 * NV; idx += 512) {
        int od = idx / NV, v = idx - od * NV;
        const float4* cv = (const float4*)(csS + v * 516);
        const float4* wr = (const float4*)(wkS + od * ND);
        float a0 = 0.f, a1 = 0.f, a2 = 0.f, a3 = 0.f;
        #pragma unroll 8
        for (int c = 0; c < 128; c += 4) {
            float4 u0 = cv[c],     w0 = wr[c];
            float4 u1 = cv[c + 1], w1 = wr[c + 1];
            float4 u2 = cv[c + 2], w2 = wr[c + 2];
            float4 u3 = cv[c + 3], w3 = wr[c + 3];
            a0 += u0.x * w0.x + u0.y * w0.y + u0.z * w0.z + u0.w * w0.w;
            a1 += u1.x * w1.x + u1.y * w1.y + u1.z * w1.z + u1.w * w1.w;
            a2 += u2.x * w2.x + u2.y * w2.y + u2.z * w2.z + u2.w * w2.w;
            a3 += u3.x * w3.x + u3.y * w3.y + u3.z * w3.z + u3.w * w3.w;
        }
        g_csumWT[b * G3 * NQ + (o0 + od) * NQ + v] = (a0 + a1) + (a2 + a3);
    }
}

// ---------------- in-place softmax over views (iter0) ----------------
__global__ void k_sm(float* __restrict__ a) {
    int row = blockIdx.x;
    int lane = threadIdx.x;
    float x1 = a[row * NV + lane];
    float x2 = (lane + 32 < NV) ? a[row * NV + lane + 32] : -1e30f;
    float m = fmaxf(x1, x2);
    for (int o = 16; o; o >>= 1) m = fmaxf(m, __shfl_xor_sync(~0u, m, o));
    float e1 = expf(x1 - m);
    float e2 = (lane + 32 < NV) ? expf(x2 - m) : 0.f;
    float s = e1 + e2;
    for (int o = 16; o; o >>= 1) s += __shfl_xor_sync(~0u, s, o);
    float inv = 1.f / s;
    a[row * NV + lane] = e1 * inv;
    if (lane + 32 < NV) a[row * NV + lane + 32] = e2 * inv;
}

// ---------------- iters 1,2: streaming dots + fused softmax ----------------
__global__ __launch_bounds__(256) void k_d(const float* __restrict__ ctx,
                                           float* __restrict__ attnT) {
    int tile = blockIdx.x, b = blockIdx.y;
    int t = threadIdx.x, lane = t & 31, w = t >> 5;
    __shared__ float dotsS[72];
    const float4* wb = (const float4*)(g_w + b * ND);
    float4 w0 = wb[lane], w1 = wb[lane + 32], w2 = wb[lane + 64], w3 = wb[lane + 96];
    int row0 = tile * 72 + w * 9;
    const float4* base = (const float4*)ctx + ((size_t)b * (NL * NV) + row0) * (ND / 4);
    float pp[9];
    #pragma unroll
    for (int r = 0; r < 9; r++) {
        const float4* p = base + r * (ND / 4);
        float4 c0 = p[lane], c1 = p[lane + 32], c2 = p[lane + 64], c3 = p[lane + 96];
        pp[r] = c0.x * w0.x + c0.y * w0.y + c0.z * w0.z + c0.w * w0.w
              + c1.x * w1.x + c1.y * w1.y + c1.z * w1.z + c1.w * w1.w
              + c2.x * w2.x + c2.y * w2.y + c2.z * w2.z + c2.w * w2.w
              + c3.x * w3.x + c3.y * w3.y + c3.z * w3.z + c3.w * w3.w;
    }
    #pragma unroll
    for (int r = 0; r < 9; r++) {
        float v = pp[r];
        for (int o = 16; o; o >>= 1) v += __shfl_xor_sync(~0u, v, o);
        if (lane == 0) dotsS[w * 9 + r] = v;
    }
    __syncthreads();
    if (w < 2) {
        float x1 = dotsS[w * 36 + lane];
        float x2 = (lane < 4) ? dotsS[w * 36 + lane + 32] : -1e30f;
        float m = fmaxf(x1, x2);
        for (int o = 16; o; o >>= 1) m = fmaxf(m, __shfl_xor_sync(~0u, m, o));
        float e1 = expf(x1 - m);
        float e2 = (lane < 4) ? expf(x2 - m) : 0.f;
        float s = e1 + e2;
        for (int o = 16; o; o >>= 1) s += __shfl_xor_sync(~0u, s, o);
        float inv = 1.f / s;
        int l = tile * 2 + w;
        float* arow = attnT + (b * NL + l) * NV;
        arow[lane] = e1 * inv;
        if (lane < 4) arow[lane + 32] = e2 * inv;
    }
}

// ---------------- fused GRU + LN + MLP (+ next-iteration w) per batch ----------------
__global__ __launch_bounds__(512) void k_g(const float* __restrict__ attnT,
                                           const float* __restrict__ slots_prev, int bstride,
                                           const float* __restrict__ Whh,
                                           const float* __restrict__ bhh,
                                           const float* __restrict__ lnfg, const float* __restrict__ lnfb,
                                           const float* __restrict__ W1, const float* __restrict__ b1,
                                           const float* __restrict__ W2, const float* __restrict__ b2,
                                           const float* __restrict__ lsg, const float* __restrict__ lsb,
                                           const float* __restrict__ Wq, const float* __restrict__ Wk,
                                           int do_w,
                                           float* __restrict__ slots_out) {
    extern __shared__ float sm[];
    float* attnS = sm;              // 1296
    float* hpS   = attnS + 1296;    // 1296
    float* gxS   = hpS + 1296;      // 3888 (reused as outS)
    float* ghS   = gxS + 3888;      // 3888 (reused as lnS/lnsum/qsum)
    float* gnewS = ghS + 3888;      // 1296
    float* ffS   = gnewS + 1296;    // 1296
    float* hidS  = ffS + 1296;      // 36*512
    float* W2S   = hidS + NQ * NH;  // 36*516
    float* outS  = gxS;
    float* lnS   = ghS;
    float* lnsum = ghS + 1296;
    float* qsum  = ghS + 1296 + 64;
    int b = blockIdx.x;
    int t = threadIdx.x, lane = t & 31, wp = t >> 5;

    for (int i = t; i < 1296; i += 512) {
        attnS[i] = attnT[b * 1296 + i];
        hpS[i] = slots_prev[(size_t)bstride * b + i];
    }
    for (int i = t; i < NQ * NH; i += 512) {
        int q = i >> 9, c = i & 511;
        W2S[q * 516 + c] = W2[i];
    }
    __syncthreads();

    for (int idx = t; idx < NQ * G3; idx += 512) {
        int i = idx / G3, o = idx - i * G3;
        u64 a0 = 0, a1 = 0;
        const ulonglong2* ar = (const ulonglong2*)(attnS + i * NQ);
        const ulonglong2* cw = (const ulonglong2*)(g_csumWT + b * G3 * NQ + o * NQ);
        #pragma unroll
        for (int c = 0; c < 9; c++) {
            ulonglong2 u = ar[c], v = cw[c];
            ffma2(a0, u.x, v.x);
            ffma2(a1, u.y, v.y);
        }
        gxS[idx] = g_gk[(b * NQ + i) * G3 + o] + hsum2(a0) + hsum2(a1);
        u64 h0 = 0, h1 = 0;
        const ulonglong2* hr = (const ulonglong2*)(hpS + i * NQ);
        const ulonglong2* wh = (const ulonglong2*)(Whh + o * NQ);
        #pragma unroll
        for (int c = 0; c < 9; c++) {
            ulonglong2 u = hr[c], v = wh[c];
            ffma2(h0, u.x, v.x);
            ffma2(h1, u.y, v.y);
        }
        ghS[idx] = bhh[o] + hsum2(h0) + hsum2(h1);
    }
    __syncthreads();

    for (int idx = t; idx < 1296; idx += 512) {
        int i = idx / NQ, qq = idx - i * NQ;
        float r = 1.f / (1.f + expf(-(gxS[i * G3 + qq] + ghS[i * G3 + qq])));
        float z = 1.f / (1.f + expf(-(gxS[i * G3 + NQ + qq] + ghS[i * G3 + NQ + qq])));
        float n = tanhf(gxS[i * G3 + 2 * NQ + qq] + r * ghS[i * G3 + 2 * NQ + qq]);
        gnewS[idx] = (1.f - z) * n + z * hpS[idx];
    }
    __syncthreads();

    for (int i = wp; i < NQ; i += 16) {
        float v1 = (lane < NQ) ? gnewS[i * NQ + lane] : 0.f;
        float v2 = (lane < 4)  ? gnewS[i * NQ + lane + 32] : 0.f;
        float s = v1 + v2;
        for (int o = 16; o; o >>= 1) s += __shfl_xor_sync(~0u, s, o);
        float mu = s * (1.f / 36.f);
        float d1 = (lane < NQ) ? (v1 - mu) : 0.f;
        float d2 = (lane < 4)  ? (v2 - mu) : 0.f;
        float vv = d1 * d1 + d2 * d2;
        for (int o = 16; o; o >>= 1) vv += __shfl_xor_sync(~0u, vv, o);
        float inv = rsqrtf(vv * (1.f / 36.f) + 1e-5f);
        if (lane < NQ) ffS[i * NQ + lane]      = d1 * inv * lnfg[lane] + lnfb[lane];
        if (lane < 4)  ffS[i * NQ + lane + 32] = d2 * inv * lnfg[lane + 32] + lnfb[lane + 32];
    }
    __syncthreads();

    {
        int h = t;
        ulonglong2 w1p[9];
        const ulonglong2* wr = (const ulonglong2*)(W1 + h * NQ);
        #pragma unroll
        for (int c = 0; c < 9; c++) w1p[c] = wr[c];
        float bb = b1[h];
        for (int i = 0; i < NQ; i++) {
            u64 a0 = 0, a1 = 0;
            const ulonglong2* fr = (const ulonglong2*)(ffS + i * NQ);
            #pragma unroll
            for (int c = 0; c < 9; c++) {
                ulonglong2 u = fr[c];
                ffma2(a0, u.x, w1p[c].x);
                ffma2(a1, u.y, w1p[c].y);
            }
            hidS[i * NH + h] = fmaxf(bb + hsum2(a0) + hsum2(a1), 0.f);
        }
    }
    __syncthreads();

    for (int idx = t; idx < 1296; idx += 512) {
        int i = idx / NQ, qq = idx - i * NQ;
        u64 a0 = 0, a1 = 0;
        const ulonglong2* hr = (const ulonglong2*)(hidS + i * NH);
        const ulonglong2* wr = (const ulonglong2*)(W2S + qq * 516);
        #pragma unroll 8
        for (int c = 0; c < NH / 4; c++) {
            ulonglong2 u = hr[c], v = wr[c];
            ffma2(a0, u.x, v.x);
            ffma2(a1, u.y, v.y);
        }
        float val = gnewS[idx] + b2[qq] + hsum2(a0) + hsum2(a1);
        slots_out[b * 1296 + idx] = val;
        outS[idx] = val;
    }

    if (!do_w) return;
    __syncthreads();

    for (int i = wp; i < NQ; i += 16) {
        float v1 = (lane < NQ) ? outS[i * NQ + lane] : 0.f;
        float v2 = (lane < 4)  ? outS[i * NQ + lane + 32] : 0.f;
        float s = v1 + v2;
        for (int o = 16; o; o >>= 1) s += __shfl_xor_sync(~0u, s, o);
        float mu = s * (1.f / 36.f);
        float d1 = (lane < NQ) ? (v1 - mu) : 0.f;
        float d2 = (lane < 4)  ? (v2 - mu) : 0.f;
        float vv = d1 * d1 + d2 * d2;
        for (int o = 16; o; o >>= 1) vv += __shfl_xor_sync(~0u, vv, o);
        float inv = rsqrtf(vv * (1.f / 36.f) + 1e-5f);
        if (lane < NQ) lnS[i * NQ + lane]      = d1 * inv * lsg[lane] + lsb[lane];
        if (lane < 4)  lnS[i * NQ + lane + 32] = d2 * inv * lsg[lane + 32] + lsb[lane + 32];
    }
    __syncthreads();
    if (t < NQ) {
        float s = 0.f;
        for (int i = 0; i < NQ; i++) s += lnS[i * NQ + t];
        lnsum[t] = s;
    }
    __syncthreads();
    if (t < NQ) {
        float s = 0.f;
        #pragma unroll 4
        for (int e = 0; e < NQ; e++) s += lnsum[e] * Wq[t * NQ + e];
        qsum[t] = s;
    }
    __syncthreads();
    {
        float s = 0.f;
        #pragma unroll 4
        for (int d = 0; d < NQ; d++) s += qsum[d] * Wk[d * CKDIM + t];
        g_w[b * ND + t] = s * (1.f / 6.f);
    }
}

static const int KG_SMEM = (1296 + 1296 + 3888 + 3888 + 1296 + 1296 + NQ * NH + NQ * 516) * 4;
static const int KP_SMEM = (NV * 516 + 27 * ND) * 4;

extern "C" void kernel_launch(void* const* d_in, const int* in_sizes, int n_in,
                              void* d_out, int out_size) {
    const float* ctx  = (const float*)d_in[1];
    const float* kn   = (const float*)d_in[4];
    const float* pano = (const float*)d_in[5];
    const float* Wq   = (const float*)d_in[6];
    const float* Wk   = (const float*)d_in[7];
    const float* Wih  = (const float*)d_in[8];
    const float* Whh  = (const float*)d_in[9];
    const float* bih  = (const float*)d_in[10];
    const float* bhh  = (const float*)d_in[11];
    const float* lsg  = (const float*)d_in[12];
    const float* lsb  = (const float*)d_in[13];
    const float* lfg  = (const float*)d_in[14];
    const float* lfb  = (const float*)d_in[15];
    const float* W1   = (const float*)d_in[16];
    const float* b1   = (const float*)d_in[17];
    const float* W2   = (const float*)d_in[18];
    const float* b2   = (const float*)d_in[19];

    float* out = (float*)d_out;
    float* slots = out;                       // [B,36,36]; attn slabs follow

    cudaFuncSetAttribute(k_g, cudaFuncAttributeMaxDynamicSharedMemorySize, KG_SMEM);
    cudaFuncSetAttribute(k_projW, cudaFuncAttributeMaxDynamicSharedMemorySize, KP_SMEM);

    k_prep<<<(G3 * ND + 255) / 256, 256>>>(Wih);
    k_gk<<<NB * NL, 128>>>(kn, bih);
    k_w<<<NB, 256>>>(pano, 0, lsg, lsb, Wq, Wk);

    for (int it = 0; it < 3; it++) {
        float* attnT = out + NB * NL * NV * (1 + it);
        const float* sp = it ? (const float*)slots : pano;
        int bs = it ? 1296 : 0;
        if (it == 0) {
            k_cd<<<dim3(NV, NB), 128>>>(ctx, attnT);
            k_projW<<<dim3(NB, 4), 512, KP_SMEM>>>();
            k_sm<<<NB * NL, 32>>>(attnT);
        } else {
            k_d<<<dim3(18, NB), 256>>>(ctx, attnT);
        }
        k_g<<<NB, 512, KG_SMEM>>>(attnT, sp, bs, Whh, bhh, lfg, lfb, W1, b1, W2, b2,
                                  lsg, lsb, Wq, Wk, it < 2 ? 1 : 0, slots);
    }
}

// round 7
// speedup vs baseline: 1.3688x; 1.0178x over previous
#include <cuda_runtime.h>

#define NB 128
#define NL 36
#define NV 36
#define ND 512
#define NKV 112
#define NQ 36
#define NH 512
#define G3 108
#define CKDIM 812   // D + KD
#define XDIM 624    // D + KV
#define HP 516      // padded pitch for hidS/W2S (conflict-free LDS.128)

typedef unsigned long long u64;

__device__ __forceinline__ void ffma2(u64& d, u64 a, u64 b) {
    asm("fma.rn.f32x2 %0, %1, %2, %0;" : "+l"(d) : "l"(a), "l"(b));
}
__device__ __forceinline__ float hsum2(u64 v) {
    float lo, hi;
    asm("mov.b64 {%0,%1}, %2;" : "=f"(lo), "=f"(hi) : "l"(v));
    return lo + hi;
}

// ---------------- scratch ----------------
__device__ float g_csum[NB * NV * ND];
__device__ float g_csumWT[NB * G3 * NQ];  // [b][o][v]
__device__ float g_gk[NB * NL * G3];
__device__ float g_w[NB * ND];
__device__ float g_WihuO[G3 * ND];
__device__ float g_WihkT[NKV * G3];

// ---------------- weight prep ----------------
__global__ void k_prep(const float* __restrict__ Wih) {
    int i = blockIdx.x * blockDim.x + threadIdx.x;
    if (i < G3 * ND)  { int o = i / ND, c = i % ND; g_WihuO[i] = Wih[o * XDIM + c]; }
    if (i < NKV * G3) { int c = i / G3, o = i % G3; g_WihkT[i] = Wih[o * XDIM + ND + c]; }
}

// ---------------- gk = knowledge @ Wih_k^T + bih ----------------
__global__ void k_gk(const float* __restrict__ kn, const float* __restrict__ bih) {
    __shared__ float knS[NKV];
    int row = blockIdx.x;
    int t = threadIdx.x;
    if (t < NKV) knS[t] = kn[row * NKV + t];
    __syncthreads();
    if (t < G3) {
        float acc = bih[t];
        #pragma unroll 4
        for (int c = 0; c < NKV; c++) acc += knS[c] * g_WihkT[c * G3 + t];
        g_gk[row * G3 + t] = acc;
    }
}

// ---------------- iter-0 projection vector (from pano) ----------------
__global__ void k_w(const float* __restrict__ slots, int bstride,
                    const float* __restrict__ lng, const float* __restrict__ lnb,
                    const float* __restrict__ Wq, const float* __restrict__ Wk) {
    int b = blockIdx.x;
    int t = threadIdx.x, lane = t & 31, wid = t >> 5;
    __shared__ float lnS[NQ * NQ];
    __shared__ float lnsum[NQ];
    __shared__ float qsum[NQ];
    const float* sp = slots + (size_t)bstride * b;
    for (int i = wid; i < NQ; i += 8) {
        float v1 = (lane < NQ)      ? sp[i * NQ + lane]      : 0.f;
        float v2 = (lane < NQ - 32) ? sp[i * NQ + lane + 32] : 0.f;
        float s = v1 + v2;
        for (int o = 16; o; o >>= 1) s += __shfl_xor_sync(~0u, s, o);
        float mu = s * (1.f / 36.f);
        float d1 = (lane < NQ) ? (v1 - mu) : 0.f;
        float d2 = (lane < NQ - 32) ? (v2 - mu) : 0.f;
        float vv = d1 * d1 + d2 * d2;
        for (int o = 16; o; o >>= 1) vv += __shfl_xor_sync(~0u, vv, o);
        float inv = rsqrtf(vv * (1.f / 36.f) + 1e-5f);
        if (lane < NQ)      lnS[i * NQ + lane]      = d1 * inv * lng[lane] + lnb[lane];
        if (lane < NQ - 32) lnS[i * NQ + lane + 32] = d2 * inv * lng[lane + 32] + lnb[lane + 32];
    }
    __syncthreads();
    if (t < NQ) {
        float s = 0.f;
        for (int i = 0; i < NQ; i++) s += lnS[i * NQ + t];
        lnsum[t] = s;
    }
    __syncthreads();
    if (t < NQ) {
        float s = 0.f;
        #pragma unroll 4
        for (int e = 0; e < NQ; e++) s += lnsum[e] * Wq[t * NQ + e];
        qsum[t] = s;
    }
    __syncthreads();
    for (int c = t; c < ND; c += blockDim.x) {
        float s = 0.f;
        #pragma unroll 4
        for (int d = 0; d < NQ; d++) s += qsum[d] * Wk[d * CKDIM + c];
        g_w[b * ND + c] = s * (1.f / 6.f);
    }
}

// ---------------- fused iter-0: csum + dots in ONE context pass ----------------
__global__ __launch_bounds__(128) void k_cd(const float* __restrict__ ctx,
                                            float* __restrict__ dots0) {
    int v = blockIdx.x, b = blockIdx.y;
    int t = threadIdx.x, lane = t & 31, w = t >> 5;
    __shared__ float ppS[NL * 129];
    const float4* wb = (const float4*)(g_w + b * ND);
    float4 w4 = wb[t];
    float4 acc = {0.f, 0.f, 0.f, 0.f};
    const float4* base = (const float4*)ctx + ((size_t)b * NL * NV + v) * (ND / 4) + t;
    #pragma unroll 4
    for (int l = 0; l < NL; l++) {
        float4 c = base[(size_t)l * NV * (ND / 4)];
        acc.x += c.x; acc.y += c.y; acc.z += c.z; acc.w += c.w;
        ppS[l * 129 + t] = c.x * w4.x + c.y * w4.y + c.z * w4.z + c.w * w4.w;
    }
    ((float4*)g_csum)[(b * NV + v) * (ND / 4) + t] = acc;
    __syncthreads();
    for (int l = w; l < NL; l += 4) {
        float s = ppS[l * 129 + lane] + ppS[l * 129 + lane + 32]
                + ppS[l * 129 + lane + 64] + ppS[l * 129 + lane + 96];
        for (int o = 16; o; o >>= 1) s += __shfl_xor_sync(~0u, s, o);
        if (lane == 0) dots0[(b * NL + l) * NV + v] = s;
    }
}

// ---------------- projection: csumWT[b] = Wihu @ csum[b]^T ----------------
__global__ __launch_bounds__(512) void k_projW() {
    int b = blockIdx.x, part = blockIdx.y;
    int t = threadIdx.x;
    extern __shared__ float sm[];
    float* csS = sm;                    // 36 rows, pitch 516
    float* wkS = sm + NV * 516;         // 27 rows, pitch 512
    const float4* src = (const float4*)(g_csum + (size_t)b * NV * ND);
    for (int i = t; i < NV * 128; i += 512) {
        int v = i >> 7, c4 = i & 127;
        ((float4*)(csS + v * 516))[c4] = src[i];
    }
    int o0 = part * 27;
    const float4* wsrc = (const float4*)(g_WihuO + o0 * ND);
    for (int i = t; i < 27 * 128; i += 512)
        ((float4*)wkS)[i] = wsrc[i];
    __syncthreads();
    for (int idx = t; idx < 27 * NV; idx += 512) {
        int od = idx / NV, v = idx - od * NV;
        const float4* cv = (const float4*)(csS + v * 516);
        const float4* wr = (const float4*)(wkS + od * ND);
        float a0 = 0.f, a1 = 0.f, a2 = 0.f, a3 = 0.f;
        #pragma unroll 8
        for (int c = 0; c < 128; c += 4) {
            float4 u0 = cv[c],     w0 = wr[c];
            float4 u1 = cv[c + 1], w1 = wr[c + 1];
            float4 u2 = cv[c + 2], w2 = wr[c + 2];
            float4 u3 = cv[c + 3], w3 = wr[c + 3];
            a0 += u0.x * w0.x + u0.y * w0.y + u0.z * w0.z + u0.w * w0.w;
            a1 += u1.x * w1.x + u1.y * w1.y + u1.z * w1.z + u1.w * w1.w;
            a2 += u2.x * w2.x + u2.y * w2.y + u2.z * w2.z + u2.w * w2.w;
            a3 += u3.x * w3.x + u3.y * w3.y + u3.z * w3.z + u3.w * w3.w;
        }
        g_csumWT[b * G3 * NQ + (o0 + od) * NQ + v] = (a0 + a1) + (a2 + a3);
    }
}

// ---------------- in-place softmax over views (iter0) ----------------
__global__ void k_sm(float* __restrict__ a) {
    int row = blockIdx.x;
    int lane = threadIdx.x;
    float x1 = a[row * NV + lane];
    float x2 = (lane + 32 < NV) ? a[row * NV + lane + 32] : -1e30f;
    float m = fmaxf(x1, x2);
    for (int o = 16; o; o >>= 1) m = fmaxf(m, __shfl_xor_sync(~0u, m, o));
    float e1 = expf(x1 - m);
    float e2 = (lane + 32 < NV) ? expf(x2 - m) : 0.f;
    float s = e1 + e2;
    for (int o = 16; o; o >>= 1) s += __shfl_xor_sync(~0u, s, o);
    float inv = 1.f / s;
    a[row * NV + lane] = e1 * inv;
    if (lane + 32 < NV) a[row * NV + lane + 32] = e2 * inv;
}

// ---------------- iters 1,2: streaming dots + softmax, k_cd-style ----------------
// block (l, b), 128 threads, 1 LDG.128 in flight per thread per v-iteration.
__global__ __launch_bounds__(128) void k_d2(const float* __restrict__ ctx,
                                            float* __restrict__ attnT) {
    int l = blockIdx.x, b = blockIdx.y;
    int t = threadIdx.x, lane = t & 31, w = t >> 5;
    __shared__ float ppS[NV * 129];
    __shared__ float dotsS[NV];
    const float4* wb = (const float4*)(g_w + b * ND);
    float4 w4 = wb[t];
    const float4* base = (const float4*)ctx + ((size_t)(b * NL + l) * NV) * (ND / 4) + t;
    #pragma unroll 4
    for (int v = 0; v < NV; v++) {
        float4 c = base[v * (ND / 4)];
        ppS[v * 129 + t] = c.x * w4.x + c.y * w4.y + c.z * w4.z + c.w * w4.w;
    }
    __syncthreads();
    for (int v = w; v < NV; v += 4) {
        float s = ppS[v * 129 + lane] + ppS[v * 129 + lane + 32]
                + ppS[v * 129 + lane + 64] + ppS[v * 129 + lane + 96];
        for (int o = 16; o; o >>= 1) s += __shfl_xor_sync(~0u, s, o);
        if (lane == 0) dotsS[v] = s;
    }
    __syncthreads();
    if (w == 0) {
        float x1 = dotsS[lane];
        float x2 = (lane < 4) ? dotsS[lane + 32] : -1e30f;
        float m = fmaxf(x1, x2);
        for (int o = 16; o; o >>= 1) m = fmaxf(m, __shfl_xor_sync(~0u, m, o));
        float e1 = expf(x1 - m);
        float e2 = (lane < 4) ? expf(x2 - m) : 0.f;
        float s = e1 + e2;
        for (int o = 16; o; o >>= 1) s += __shfl_xor_sync(~0u, s, o);
        float inv = 1.f / s;
        float* arow = attnT + (b * NL + l) * NV;
        arow[lane] = e1 * inv;
        if (lane < 4) arow[lane + 32] = e2 * inv;
    }
}

// ---------------- fused GRU + LN + MLP (+ next-iteration w), register-tiled ----------------
__global__ __launch_bounds__(512) void k_g(const float* __restrict__ attnT,
                                           const float* __restrict__ slots_prev, int bstride,
                                           const float* __restrict__ Whh,
                                           const float* __restrict__ bhh,
                                           const float* __restrict__ lnfg, const float* __restrict__ lnfb,
                                           const float* __restrict__ W1, const float* __restrict__ b1,
                                           const float* __restrict__ W2, const float* __restrict__ b2,
                                           const float* __restrict__ lsg, const float* __restrict__ lsb,
                                           const float* __restrict__ Wq, const float* __restrict__ Wk,
                                           int do_w,
                                           float* __restrict__ slots_out) {
    extern __shared__ float sm[];
    float* attnS = sm;              // 1296
    float* hpS   = attnS + 1296;    // 1296
    float* gxS   = hpS + 1296;      // 3888 (later: outS)
    float* ghS   = gxS + 3888;      // 3888 (later: partialS 2592 / lnS)
    float* gnewS = ghS + 3888;      // 1296
    float* ffS   = gnewS + 1296;    // 1296
    float* hidS  = ffS + 1296;      // 36*HP
    float* W2S   = hidS + NQ * HP;  // 36*HP
    float* outS  = gxS;
    float* partialS = ghS;
    float* lnS   = ghS;
    float* lnsum = ghS + 1296;
    float* qsum  = ghS + 1296 + 64;
    int b = blockIdx.x;
    int t = threadIdx.x, lane = t & 31, wp = t >> 5;

    for (int i = t; i < 1296; i += 512) {
        attnS[i] = attnT[b * 1296 + i];
        hpS[i] = slots_prev[(size_t)bstride * b + i];
    }
    for (int i = t; i < NQ * NH; i += 512) {
        int q = i >> 9, c = i & 511;
        W2S[q * HP + c] = W2[i];
    }
    __syncthreads();

    // (a) gx = gk + attn @ csumW^T ; gh = bhh + hp @ Whh^T  — 2x2 tiles (i,i+18)x(o,o+54)
    for (int task = t; task < 18 * 54; task += 512) {
        int i2 = task / 54, o2 = task - i2 * 54;
        const ulonglong2* ar0 = (const ulonglong2*)(attnS + i2 * NQ);
        const ulonglong2* ar1 = (const ulonglong2*)(attnS + (i2 + 18) * NQ);
        const ulonglong2* hr0 = (const ulonglong2*)(hpS + i2 * NQ);
        const ulonglong2* hr1 = (const ulonglong2*)(hpS + (i2 + 18) * NQ);
        const ulonglong2* cw0 = (const ulonglong2*)(g_csumWT + b * G3 * NQ + o2 * NQ);
        const ulonglong2* cw1 = (const ulonglong2*)(g_csumWT + b * G3 * NQ + (o2 + 54) * NQ);
        const ulonglong2* wh0 = (const ulonglong2*)(Whh + o2 * NQ);
        const ulonglong2* wh1 = (const ulonglong2*)(Whh + (o2 + 54) * NQ);
        u64 x00 = 0, x01 = 0, x10 = 0, x11 = 0;
        u64 h00 = 0, h01 = 0, h10 = 0, h11 = 0;
        #pragma unroll
        for (int j = 0; j < 9; j++) {
            ulonglong2 a0 = ar0[j], a1 = ar1[j], c0 = cw0[j], c1 = cw1[j];
            ffma2(x00, a0.x, c0.x); ffma2(x00, a0.y, c0.y);
            ffma2(x01, a0.x, c1.x); ffma2(x01, a0.y, c1.y);
            ffma2(x10, a1.x, c0.x); ffma2(x10, a1.y, c0.y);
            ffma2(x11, a1.x, c1.x); ffma2(x11, a1.y, c1.y);
            ulonglong2 p0 = hr0[j], p1 = hr1[j], q0 = wh0[j], q1 = wh1[j];
            ffma2(h00, p0.x, q0.x); ffma2(h00, p0.y, q0.y);
            ffma2(h01, p0.x, q1.x); ffma2(h01, p0.y, q1.y);
            ffma2(h10, p1.x, q0.x); ffma2(h10, p1.y, q0.y);
            ffma2(h11, p1.x, q1.x); ffma2(h11, p1.y, q1.y);
        }
        const float* gkb = g_gk + b * NQ * G3;
        gxS[i2 * G3 + o2]             = gkb[i2 * G3 + o2]             + hsum2(x00);
        gxS[i2 * G3 + o2 + 54]        = gkb[i2 * G3 + o2 + 54]        + hsum2(x01);
        gxS[(i2 + 18) * G3 + o2]      = gkb[(i2 + 18) * G3 + o2]      + hsum2(x10);
        gxS[(i2 + 18) * G3 + o2 + 54] = gkb[(i2 + 18) * G3 + o2 + 54] + hsum2(x11);
        ghS[i2 * G3 + o2]             = bhh[o2]      + hsum2(h00);
        ghS[i2 * G3 + o2 + 54]        = bhh[o2 + 54] + hsum2(h01);
        ghS[(i2 + 18) * G3 + o2]      = bhh[o2]      + hsum2(h10);
        ghS[(i2 + 18) * G3 + o2 + 54] = bhh[o2 + 54] + hsum2(h11);
    }
    __syncthreads();

    // GRU gates
    for (int idx = t; idx < 1296; idx += 512) {
        int i = idx / NQ, qq = idx - i * NQ;
        float r = 1.f / (1.f + expf(-(gxS[i * G3 + qq] + ghS[i * G3 + qq])));
        float z = 1.f / (1.f + expf(-(gxS[i * G3 + NQ + qq] + ghS[i * G3 + NQ + qq])));
        float n = tanhf(gxS[i * G3 + 2 * NQ + qq] + r * ghS[i * G3 + 2 * NQ + qq]);
        gnewS[idx] = (1.f - z) * n + z * hpS[idx];
    }
    __syncthreads();

    // LayerNorm rows of gnew
    for (int i = wp; i < NQ; i += 16) {
        float v1 = (lane < NQ) ? gnewS[i * NQ + lane] : 0.f;
        float v2 = (lane < 4)  ? gnewS[i * NQ + lane + 32] : 0.f;
        float s = v1 + v2;
        for (int o = 16; o; o >>= 1) s += __shfl_xor_sync(~0u, s, o);
        float mu = s * (1.f / 36.f);
        float d1 = (lane < NQ) ? (v1 - mu) : 0.f;
        float d2 = (lane < 4)  ? (v2 - mu) : 0.f;
        float vv = d1 * d1 + d2 * d2;
        for (int o = 16; o; o >>= 1) vv += __shfl_xor_sync(~0u, vv, o);
        float inv = rsqrtf(vv * (1.f / 36.f) + 1e-5f);
        if (lane < NQ) ffS[i * NQ + lane]      = d1 * inv * lnfg[lane] + lnfb[lane];
        if (lane < 4)  ffS[i * NQ + lane + 32] = d2 * inv * lnfg[lane + 32] + lnfb[lane + 32];
    }
    __syncthreads();

    // (b) hidden = relu(ff @ W1^T + b1): thread = h, W1 row in regs, fr broadcast
    {
        int h = t;
        ulonglong2 w1p[9];
        const ulonglong2* wr = (const ulonglong2*)(W1 + h * NQ);
        #pragma unroll
        for (int c = 0; c < 9; c++) w1p[c] = wr[c];
        float bb = b1[h];
        for (int i = 0; i < NQ; i++) {
            u64 a0 = 0, a1 = 0;
            const ulonglong2* fr = (const ulonglong2*)(ffS + i * NQ);
            #pragma unroll
            for (int c = 0; c < 9; c++) {
                ulonglong2 u = fr[c];
                ffma2(a0, u.x, w1p[c].x);
                ffma2(a1, u.y, w1p[c].y);
            }
            hidS[i * HP + h] = fmaxf(bb + hsum2(a0) + hsum2(a1), 0.f);
        }
    }
    __syncthreads();

    // (c) out = gnew + hidden @ W2^T + b2 — 2x2 tiles (i,i+18)x(q,q+18), d split 2
    for (int task = t; task < 648; task += 512) {
        int dh = task / 324;
        int tile = task - dh * 324;
        int i2 = tile / 18, q2 = tile - i2 * 18;
        const ulonglong2* H0 = (const ulonglong2*)(hidS + i2 * HP) + dh * 64;
        const ulonglong2* H1 = (const ulonglong2*)(hidS + (i2 + 18) * HP) + dh * 64;
        const ulonglong2* V0 = (const ulonglong2*)(W2S + q2 * HP) + dh * 64;
        const ulonglong2* V1 = (const ulonglong2*)(W2S + (q2 + 18) * HP) + dh * 64;
        u64 a00 = 0, a01 = 0, a10 = 0, a11 = 0;
        #pragma unroll 8
        for (int c = 0; c < 64; c++) {
            ulonglong2 u0 = H0[c], u1 = H1[c], v0 = V0[c], v1 = V1[c];
            ffma2(a00, u0.x, v0.x); ffma2(a00, u0.y, v0.y);
            ffma2(a01, u0.x, v1.x); ffma2(a01, u0.y, v1.y);
            ffma2(a10, u1.x, v0.x); ffma2(a10, u1.y, v0.y);
            ffma2(a11, u1.x, v1.x); ffma2(a11, u1.y, v1.y);
        }
        float* ps = partialS + dh * 1296;
        ps[i2 * NQ + q2]             = hsum2(a00);
        ps[i2 * NQ + q2 + 18]        = hsum2(a01);
        ps[(i2 + 18) * NQ + q2]      = hsum2(a10);
        ps[(i2 + 18) * NQ + q2 + 18] = hsum2(a11);
    }
    __syncthreads();

    for (int idx = t; idx < 1296; idx += 512) {
        int qq = idx % NQ;
        float val = gnewS[idx] + b2[qq] + partialS[idx] + partialS[1296 + idx];
        slots_out[b * 1296 + idx] = val;
        outS[idx] = val;
    }

    if (!do_w) return;
    __syncthreads();

    // fused next-iteration w
    for (int i = wp; i < NQ; i += 16) {
        float v1 = (lane < NQ) ? outS[i * NQ + lane] : 0.f;
        float v2 = (lane < 4)  ? outS[i * NQ + lane + 32] : 0.f;
        float s = v1 + v2;
        for (int o = 16; o; o >>= 1) s += __shfl_xor_sync(~0u, s, o);
        float mu = s * (1.f / 36.f);
        float d1 = (lane < NQ) ? (v1 - mu) : 0.f;
        float d2 = (lane < 4)  ? (v2 - mu) : 0.f;
        float vv = d1 * d1 + d2 * d2;
        for (int o = 16; o; o >>= 1) vv += __shfl_xor_sync(~0u, vv, o);
        float inv = rsqrtf(vv * (1.f / 36.f) + 1e-5f);
        if (lane < NQ) lnS[i * NQ + lane]      = d1 * inv * lsg[lane] + lsb[lane];
        if (lane < 4)  lnS[i * NQ + lane + 32] = d2 * inv * lsg[lane + 32] + lsb[lane + 32];
    }
    __syncthreads();
    if (t < NQ) {
        float s = 0.f;
        for (int i = 0; i < NQ; i++) s += lnS[i * NQ + t];
        lnsum[t] = s;
    }
    __syncthreads();
    if (t < NQ) {
        float s = 0.f;
        #pragma unroll 4
        for (int e = 0; e < NQ; e++) s += lnsum[e] * Wq[t * NQ + e];
        qsum[t] = s;
    }
    __syncthreads();
    {
        float s = 0.f;
        #pragma unroll 4
        for (int d = 0; d < NQ; d++) s += qsum[d] * Wk[d * CKDIM + t];
        g_w[b * ND + t] = s * (1.f / 6.f);
    }
}

static const int KG_SMEM = (1296 + 1296 + 3888 + 3888 + 1296 + 1296 + NQ * HP + NQ * HP) * 4;
static const int KP_SMEM = (NV * 516 + 27 * ND) * 4;

extern "C" void kernel_launch(void* const* d_in, const int* in_sizes, int n_in,
                              void* d_out, int out_size) {
    const float* ctx  = (const float*)d_in[1];
    const float* kn   = (const float*)d_in[4];
    const float* pano = (const float*)d_in[5];
    const float* Wq   = (const float*)d_in[6];
    const float* Wk   = (const float*)d_in[7];
    const float* Wih  = (const float*)d_in[8];
    const float* Whh  = (const float*)d_in[9];
    const float* bih  = (const float*)d_in[10];
    const float* bhh  = (const float*)d_in[11];
    const float* lsg  = (const float*)d_in[12];
    const float* lsb  = (const float*)d_in[13];
    const float* lfg  = (const float*)d_in[14];
    const float* lfb  = (const float*)d_in[15];
    const float* W1   = (const float*)d_in[16];
    const float* b1   = (const float*)d_in[17];
    const float* W2   = (const float*)d_in[18];
    const float* b2   = (const float*)d_in[19];

    float* out = (float*)d_out;
    float* slots = out;                       // [B,36,36]; attn slabs follow

    cudaFuncSetAttribute(k_g, cudaFuncAttributeMaxDynamicSharedMemorySize, KG_SMEM);
    cudaFuncSetAttribute(k_projW, cudaFuncAttributeMaxDynamicSharedMemorySize, KP_SMEM);

    k_prep<<<(G3 * ND + 255) / 256, 256>>>(Wih);
    k_gk<<<NB * NL, 128>>>(kn, bih);
    k_w<<<NB, 256>>>(pano, 0, lsg, lsb, Wq, Wk);

    for (int it = 0; it < 3; it++) {
        float* attnT = out + NB * NL * NV * (1 + it);
        const float* sp = it ? (const float*)slots : pano;
        int bs = it ? 1296 : 0;
        if (it == 0) {
            k_cd<<<dim3(NV, NB), 128>>>(ctx, attnT);
            k_projW<<<dim3(NB, 4), 512, KP_SMEM>>>();
            k_sm<<<NB * NL, 32>>>(attnT);
        } else {
            k_d2<<<dim3(NL, NB), 128>>>(ctx, attnT);
        }
        k_g<<<NB, 512, KG_SMEM>>>(attnT, sp, bs, Whh, bhh, lfg, lfb, W1, b1, W2, b2,
                                  lsg, lsb, Wq, Wk, it < 2 ? 1 : 0, slots);
    }
}

// round 8
// speedup vs baseline: 1.5264x; 1.1152x over previous
#include <cuda_runtime.h>

#define NB 128
#define NL 36
#define NV 36
#define ND 512
#define NKV 112
#define NQ 36
#define NH 512
#define G3 108
#define CKDIM 812   // D + KD
#define XDIM 624    // D + KV
#define HP 516      // padded pitch (conflict-free LDS.128)

typedef unsigned long long u64;

__device__ __forceinline__ void ffma2(u64& d, u64 a, u64 b) {
    asm("fma.rn.f32x2 %0, %1, %2, %0;" : "+l"(d) : "l"(a), "l"(b));
}
__device__ __forceinline__ float hsum2(u64 v) {
    float lo, hi;
    asm("mov.b64 {%0,%1}, %2;" : "=f"(lo), "=f"(hi) : "l"(v));
    return lo + hi;
}

// ---------------- scratch ----------------
__device__ float g_csum[NB * NV * ND];
__device__ float g_csumWT[NB * G3 * NQ];  // [b][o][v]
__device__ float g_gk[NB * NL * G3];
__device__ float g_w[NB * ND];
__device__ float g_WihuO[G3 * ND];
__device__ float g_WihkT[NKV * G3];

// ---------------- weight prep ----------------
__global__ void k_prep(const float* __restrict__ Wih) {
    int i = blockIdx.x * blockDim.x + threadIdx.x;
    if (i < G3 * ND)  { int o = i / ND, c = i % ND; g_WihuO[i] = Wih[o * XDIM + c]; }
    if (i < NKV * G3) { int c = i / G3, o = i % G3; g_WihkT[i] = Wih[o * XDIM + ND + c]; }
}

// ---------------- gk = knowledge @ Wih_k^T + bih ----------------
__global__ void k_gk(const float* __restrict__ kn, const float* __restrict__ bih) {
    __shared__ float knS[NKV];
    int row = blockIdx.x;
    int t = threadIdx.x;
    if (t < NKV) knS[t] = kn[row * NKV + t];
    __syncthreads();
    if (t < G3) {
        float acc = bih[t];
        #pragma unroll 4
        for (int c = 0; c < NKV; c++) acc += knS[c] * g_WihkT[c * G3 + t];
        g_gk[row * G3 + t] = acc;
    }
}

// ---------------- projection vector w (per-iteration, from slots or pano) ----------------
__global__ void k_w(const float* __restrict__ slots, int bstride,
                    const float* __restrict__ lng, const float* __restrict__ lnb,
                    const float* __restrict__ Wq, const float* __restrict__ Wk) {
    int b = blockIdx.x;
    int t = threadIdx.x, lane = t & 31, wid = t >> 5;
    __shared__ float lnS[NQ * NQ];
    __shared__ float lnsum[NQ];
    __shared__ float qsum[NQ];
    const float* sp = slots + (size_t)bstride * b;
    for (int i = wid; i < NQ; i += 8) {
        float v1 = (lane < NQ)      ? sp[i * NQ + lane]      : 0.f;
        float v2 = (lane < NQ - 32) ? sp[i * NQ + lane + 32] : 0.f;
        float s = v1 + v2;
        for (int o = 16; o; o >>= 1) s += __shfl_xor_sync(~0u, s, o);
        float mu = s * (1.f / 36.f);
        float d1 = (lane < NQ) ? (v1 - mu) : 0.f;
        float d2 = (lane < NQ - 32) ? (v2 - mu) : 0.f;
        float vv = d1 * d1 + d2 * d2;
        for (int o = 16; o; o >>= 1) vv += __shfl_xor_sync(~0u, vv, o);
        float inv = rsqrtf(vv * (1.f / 36.f) + 1e-5f);
        if (lane < NQ)      lnS[i * NQ + lane]      = d1 * inv * lng[lane] + lnb[lane];
        if (lane < NQ - 32) lnS[i * NQ + lane + 32] = d2 * inv * lng[lane + 32] + lnb[lane + 32];
    }
    __syncthreads();
    if (t < NQ) {
        float s = 0.f;
        for (int i = 0; i < NQ; i++) s += lnS[i * NQ + t];
        lnsum[t] = s;
    }
    __syncthreads();
    if (t < NQ) {
        float s = 0.f;
        #pragma unroll 4
        for (int e = 0; e < NQ; e++) s += lnsum[e] * Wq[t * NQ + e];
        qsum[t] = s;
    }
    __syncthreads();
    for (int c = t; c < ND; c += blockDim.x) {
        float s = 0.f;
        #pragma unroll 4
        for (int d = 0; d < NQ; d++) s += qsum[d] * Wk[d * CKDIM + c];
        g_w[b * ND + c] = s * (1.f / 6.f);
    }
}

// ---------------- fused iter-0: csum + dots, two 18-row chunks (small smem) ----------------
__global__ __launch_bounds__(128) void k_cd(const float* __restrict__ ctx,
                                            float* __restrict__ dots0) {
    int v = blockIdx.x, b = blockIdx.y;
    int t = threadIdx.x, lane = t & 31, w = t >> 5;
    __shared__ float ppS[18 * 129];
    const float4* wb = (const float4*)(g_w + b * ND);
    float4 w4 = wb[t];
    float4 acc = {0.f, 0.f, 0.f, 0.f};
    const float4* base = (const float4*)ctx + ((size_t)b * NL * NV + v) * (ND / 4) + t;
    #pragma unroll 1
    for (int half = 0; half < 2; half++) {
        #pragma unroll 3
        for (int li = 0; li < 18; li++) {
            int l = half * 18 + li;
            float4 c = base[(size_t)l * NV * (ND / 4)];
            acc.x += c.x; acc.y += c.y; acc.z += c.z; acc.w += c.w;
            ppS[li * 129 + t] = c.x * w4.x + c.y * w4.y + c.z * w4.z + c.w * w4.w;
        }
        __syncthreads();
        for (int li = w; li < 18; li += 4) {
            float s = ppS[li * 129 + lane] + ppS[li * 129 + lane + 32]
                    + ppS[li * 129 + lane + 64] + ppS[li * 129 + lane + 96];
            for (int o = 16; o; o >>= 1) s += __shfl_xor_sync(~0u, s, o);
            if (lane == 0) dots0[(b * NL + half * 18 + li) * NV + v] = s;
        }
        __syncthreads();
    }
    ((float4*)g_csum)[(b * NV + v) * (ND / 4) + t] = acc;
}

// ---------------- projection: csumWT[b] = Wihu @ csum[b]^T ----------------
__global__ __launch_bounds__(512) void k_projW() {
    int b = blockIdx.x, part = blockIdx.y;
    int t = threadIdx.x;
    extern __shared__ float sm[];
    float* csS = sm;                    // 36 rows, pitch 516
    float* wkS = sm + NV * 516;         // 27 rows, pitch 512
    const float4* src = (const float4*)(g_csum + (size_t)b * NV * ND);
    for (int i = t; i < NV * 128; i += 512) {
        int v = i >> 7, c4 = i & 127;
        ((float4*)(csS + v * 516))[c4] = src[i];
    }
    int o0 = part * 27;
    const float4* wsrc = (const float4*)(g_WihuO + o0 * ND);
    for (int i = t; i < 27 * 128; i += 512)
        ((float4*)wkS)[i] = wsrc[i];
    __syncthreads();
    for (int idx = t; idx < 27 * NV; idx += 512) {
        int od = idx / NV, v = idx - od * NV;
        const float4* cv = (const float4*)(csS + v * 516);
        const float4* wr = (const float4*)(wkS + od * ND);
        float a0 = 0.f, a1 = 0.f, a2 = 0.f, a3 = 0.f;
        #pragma unroll 8
        for (int c = 0; c < 128; c += 4) {
            float4 u0 = cv[c],     w0 = wr[c];
            float4 u1 = cv[c + 1], w1 = wr[c + 1];
            float4 u2 = cv[c + 2], w2 = wr[c + 2];
            float4 u3 = cv[c + 3], w3 = wr[c + 3];
            a0 += u0.x * w0.x + u0.y * w0.y + u0.z * w0.z + u0.w * w0.w;
            a1 += u1.x * w1.x + u1.y * w1.y + u1.z * w1.z + u1.w * w1.w;
            a2 += u2.x * w2.x + u2.y * w2.y + u2.z * w2.z + u2.w * w2.w;
            a3 += u3.x * w3.x + u3.y * w3.y + u3.z * w3.z + u3.w * w3.w;
        }
        g_csumWT[b * G3 * NQ + (o0 + od) * NQ + v] = (a0 + a1) + (a2 + a3);
    }
}

// ---------------- iters 1,2: streaming dots + softmax, two 18-row chunks ----------------
__global__ __launch_bounds__(128) void k_d2(const float* __restrict__ ctx,
                                            float* __restrict__ attnT) {
    int l = blockIdx.x, b = blockIdx.y;
    int t = threadIdx.x, lane = t & 31, w = t >> 5;
    __shared__ float ppS[18 * 129];
    __shared__ float dotsS[NV];
    const float4* wb = (const float4*)(g_w + b * ND);
    float4 w4 = wb[t];
    const float4* base = (const float4*)ctx + ((size_t)(b * NL + l) * NV) * (ND / 4) + t;
    #pragma unroll 1
    for (int half = 0; half < 2; half++) {
        #pragma unroll 3
        for (int vi = 0; vi < 18; vi++) {
            int v = half * 18 + vi;
            float4 c = base[v * (ND / 4)];
            ppS[vi * 129 + t] = c.x * w4.x + c.y * w4.y + c.z * w4.z + c.w * w4.w;
        }
        __syncthreads();
        for (int vi = w; vi < 18; vi += 4) {
            float s = ppS[vi * 129 + lane] + ppS[vi * 129 + lane + 32]
                    + ppS[vi * 129 + lane + 64] + ppS[vi * 129 + lane + 96];
            for (int o = 16; o; o >>= 1) s += __shfl_xor_sync(~0u, s, o);
            if (lane == 0) dotsS[half * 18 + vi] = s;
        }
        __syncthreads();
    }
    if (w == 0) {
        float x1 = dotsS[lane];
        float x2 = (lane < 4) ? dotsS[lane + 32] : -1e30f;
        float m = fmaxf(x1, x2);
        for (int o = 16; o; o >>= 1) m = fmaxf(m, __shfl_xor_sync(~0u, m, o));
        float e1 = expf(x1 - m);
        float e2 = (lane < 4) ? expf(x2 - m) : 0.f;
        float s = e1 + e2;
        for (int o = 16; o; o >>= 1) s += __shfl_xor_sync(~0u, s, o);
        float inv = 1.f / s;
        float* arow = attnT + (b * NL + l) * NV;
        arow[lane] = e1 * inv;
        if (lane < 4) arow[lane + 32] = e2 * inv;
    }
}

// ---------------- fused GRU + LN + MLP, split per (b, i-half). 53KB smem. ----------------
// smem layout (floats):
//   A0 [0,648)        attnS  -> gnewS after (a)/GRU
//   A1 [648,1296)     hpS    -> ffS after GRU
//   A2 [1296,2592)    sumS (18 x 72): gx+gh for r,z gates
//   A3 [2592,3240)    gxnS (18 x 36)
//   A4 [3240,3888)    ghnS (18 x 36)
//   A5 [3888,13176)   hidS (18 x 516)
#define KG2_FLOATS 13176
__global__ __launch_bounds__(512) void k_g(const float* __restrict__ attnT,
                                           const float* __restrict__ slots_prev, int bstride,
                                           const float* __restrict__ Whh,
                                           const float* __restrict__ bhh,
                                           const float* __restrict__ lnfg, const float* __restrict__ lnfb,
                                           const float* __restrict__ W1, const float* __restrict__ b1,
                                           const float* __restrict__ W2, const float* __restrict__ b2,
                                           int do_sm,
                                           float* __restrict__ attnT_out,
                                           float* __restrict__ slots_out) {
    extern __shared__ float sm[];
    float* attnS = sm;            // -> gnewS
    float* hpS   = sm + 648;      // -> ffS
    float* sumS  = sm + 1296;
    float* gxnS  = sm + 2592;
    float* ghnS  = sm + 3240;
    float* hidS  = sm + 3888;
    float* gnewS = attnS;
    float* ffS   = hpS;
    int b = blockIdx.x, half = blockIdx.y;
    int t = threadIdx.x, lane = t & 31, wp = t >> 5;
    int rbase = b * 1296 + half * 648;

    for (int i = t; i < 648; i += 512) {
        attnS[i] = attnT[rbase + i];
        hpS[i] = slots_prev[(size_t)bstride * b + half * 648 + i];
    }
    __syncthreads();

    // optional softmax (iter 0: attnT holds raw dots)
    if (do_sm) {
        for (int i = wp; i < 18; i += 16) {
            float x1 = (lane < NV) ? attnS[i * NV + lane] : -1e30f;
            float x2 = (lane < 4)  ? attnS[i * NV + lane + 32] : -1e30f;
            float m = fmaxf(x1, x2);
            for (int o = 16; o; o >>= 1) m = fmaxf(m, __shfl_xor_sync(~0u, m, o));
            float e1 = (lane < NV) ? expf(x1 - m) : 0.f;
            float e2 = (lane < 4)  ? expf(x2 - m) : 0.f;
            float s = e1 + e2;
            for (int o = 16; o; o >>= 1) s += __shfl_xor_sync(~0u, s, o);
            float inv = 1.f / s;
            if (lane < NV) attnS[i * NV + lane]      = e1 * inv;
            if (lane < 4)  attnS[i * NV + lane + 32] = e2 * inv;
        }
        __syncthreads();
        for (int i = t; i < 648; i += 512) attnT_out[rbase + i] = attnS[i];
    }

    // (a) gates: 2x2 tiles (i2,i2+9) x (o2,o2+54), 486 tasks
    if (t < 486) {
        int i2 = t / 54, o2 = t - i2 * 54;
        const ulonglong2* ar0 = (const ulonglong2*)(attnS + i2 * NQ);
        const ulonglong2* ar1 = (const ulonglong2*)(attnS + (i2 + 9) * NQ);
        const ulonglong2* hr0 = (const ulonglong2*)(hpS + i2 * NQ);
        const ulonglong2* hr1 = (const ulonglong2*)(hpS + (i2 + 9) * NQ);
        const ulonglong2* cw0 = (const ulonglong2*)(g_csumWT + b * G3 * NQ + o2 * NQ);
        const ulonglong2* cw1 = (const ulonglong2*)(g_csumWT + b * G3 * NQ + (o2 + 54) * NQ);
        const ulonglong2* wh0 = (const ulonglong2*)(Whh + o2 * NQ);
        const ulonglong2* wh1 = (const ulonglong2*)(Whh + (o2 + 54) * NQ);
        u64 x00 = 0, x01 = 0, x10 = 0, x11 = 0;
        u64 h00 = 0, h01 = 0, h10 = 0, h11 = 0;
        #pragma unroll
        for (int j = 0; j < 9; j++) {
            ulonglong2 a0 = ar0[j], a1 = ar1[j], c0 = cw0[j], c1 = cw1[j];
            ffma2(x00, a0.x, c0.x); ffma2(x00, a0.y, c0.y);
            ffma2(x01, a0.x, c1.x); ffma2(x01, a0.y, c1.y);
            ffma2(x10, a1.x, c0.x); ffma2(x10, a1.y, c0.y);
            ffma2(x11, a1.x, c1.x); ffma2(x11, a1.y, c1.y);
            ulonglong2 p0 = hr0[j], p1 = hr1[j], q0 = wh0[j], q1 = wh1[j];
            ffma2(h00, p0.x, q0.x); ffma2(h00, p0.y, q0.y);
            ffma2(h01, p0.x, q1.x); ffma2(h01, p0.y, q1.y);
            ffma2(h10, p1.x, q0.x); ffma2(h10, p1.y, q0.y);
            ffma2(h11, p1.x, q1.x); ffma2(h11, p1.y, q1.y);
        }
        const float* gkb = g_gk + (b * NQ + half * 18) * G3;
        // col A = o2 (< 72: r or z region) -> sum
        float gxA0 = gkb[i2 * G3 + o2] + hsum2(x00);
        float ghA0 = bhh[o2] + hsum2(h00);
        float gxA1 = gkb[(i2 + 9) * G3 + o2] + hsum2(x10);
        float ghA1 = bhh[o2] + hsum2(h10);
        sumS[i2 * 72 + o2]       = gxA0 + ghA0;
        sumS[(i2 + 9) * 72 + o2] = gxA1 + ghA1;
        // col B = o2 + 54
        int oB = o2 + 54;
        float gxB0 = gkb[i2 * G3 + oB] + hsum2(x01);
        float ghB0 = bhh[oB] + hsum2(h01);
        float gxB1 = gkb[(i2 + 9) * G3 + oB] + hsum2(x11);
        float ghB1 = bhh[oB] + hsum2(h11);
        if (o2 < 18) {  // B in z region
            sumS[i2 * 72 + oB]       = gxB0 + ghB0;
            sumS[(i2 + 9) * 72 + oB] = gxB1 + ghB1;
        } else {        // B in n region
            int on = o2 - 18;
            gxnS[i2 * NQ + on]       = gxB0;
            ghnS[i2 * NQ + on]       = ghB0;
            gxnS[(i2 + 9) * NQ + on] = gxB1;
            ghnS[(i2 + 9) * NQ + on] = ghB1;
        }
    }
    __syncthreads();

    // GRU gates -> gnew (overwrites attnS; attn is dead)
    for (int idx = t; idx < 648; idx += 512) {
        int i = idx / NQ, qq = idx - i * NQ;
        float r = 1.f / (1.f + expf(-sumS[i * 72 + qq]));
        float z = 1.f / (1.f + expf(-sumS[i * 72 + 36 + qq]));
        float n = tanhf(gxnS[idx] + r * ghnS[idx]);
        float hp = hpS[idx];
        gnewS[idx] = (1.f - z) * n + z * hp;
    }
    __syncthreads();

    // LayerNorm rows of gnew -> ff (overwrites hpS; hp is dead)
    for (int i = wp; i < 18; i += 16) {
        float v1 = (lane < NQ) ? gnewS[i * NQ + lane] : 0.f;
        float v2 = (lane < 4)  ? gnewS[i * NQ + lane + 32] : 0.f;
        float s = v1 + v2;
        for (int o = 16; o; o >>= 1) s += __shfl_xor_sync(~0u, s, o);
        float mu = s * (1.f / 36.f);
        float d1 = (lane < NQ) ? (v1 - mu) : 0.f;
        float d2 = (lane < 4)  ? (v2 - mu) : 0.f;
        float vv = d1 * d1 + d2 * d2;
        for (int o = 16; o; o >>= 1) vv += __shfl_xor_sync(~0u, vv, o);
        float inv = rsqrtf(vv * (1.f / 36.f) + 1e-5f);
        if (lane < NQ) ffS[i * NQ + lane]      = d1 * inv * lnfg[lane] + lnfb[lane];
        if (lane < 4)  ffS[i * NQ + lane + 32] = d2 * inv * lnfg[lane + 32] + lnfb[lane + 32];
    }
    __syncthreads();

    // (b) hidden = relu(ff @ W1^T + b1): thread = h
    {
        int h = t;
        ulonglong2 w1p[9];
        const ulonglong2* wr = (const ulonglong2*)(W1 + h * NQ);
        #pragma unroll
        for (int c = 0; c < 9; c++) w1p[c] = wr[c];
        float bb = b1[h];
        for (int i = 0; i < 18; i++) {
            u64 a0 = 0, a1 = 0;
            const ulonglong2* fr = (const ulonglong2*)(ffS + i * NQ);
            #pragma unroll
            for (int c = 0; c < 9; c++) {
                ulonglong2 u = fr[c];
                ffma2(a0, u.x, w1p[c].x);
                ffma2(a1, u.y, w1p[c].y);
            }
            hidS[i * HP + h] = fmaxf(bb + hsum2(a0) + hsum2(a1), 0.f);
        }
    }
    __syncthreads();

    // (c) out = gnew + hidden @ W2^T + b2 — warp per q, coalesced W2 LDG (L1-hot)
    for (int q = wp; q < NQ; q += 16) {
        ulonglong2 w2r[4];
        const ulonglong2* wr = (const ulonglong2*)(W2 + q * NH);
        #pragma unroll
        for (int k = 0; k < 4; k++) w2r[k] = wr[lane + 32 * k];
        float bq = b2[q];
        for (int i = 0; i < 18; i++) {
            const ulonglong2* hr = (const ulonglong2*)(hidS + i * HP);
            u64 a0 = 0, a1 = 0;
            #pragma unroll
            for (int k = 0; k < 4; k += 2) {
                ulonglong2 u0 = hr[lane + 32 * k];
                ulonglong2 u1 = hr[lane + 32 * (k + 1)];
                ffma2(a0, u0.x, w2r[k].x);     ffma2(a0, u0.y, w2r[k].y);
                ffma2(a1, u1.x, w2r[k + 1].x); ffma2(a1, u1.y, w2r[k + 1].y);
            }
            float p = hsum2(a0) + hsum2(a1);
            for (int o = 16; o; o >>= 1) p += __shfl_xor_sync(~0u, p, o);
            if (lane == 0)
                slots_out[rbase + i * NQ + q] = gnewS[i * NQ + q] + bq + p;
        }
    }
}

static const int KG_SMEM = KG2_FLOATS * 4;
static const int KP_SMEM = (NV * 516 + 27 * ND) * 4;

extern "C" void kernel_launch(void* const* d_in, const int* in_sizes, int n_in,
                              void* d_out, int out_size) {
    const float* ctx  = (const float*)d_in[1];
    const float* kn   = (const float*)d_in[4];
    const float* pano = (const float*)d_in[5];
    const float* Wq   = (const float*)d_in[6];
    const float* Wk   = (const float*)d_in[7];
    const float* Wih  = (const float*)d_in[8];
    const float* Whh  = (const float*)d_in[9];
    const float* bih  = (const float*)d_in[10];
    const float* bhh  = (const float*)d_in[11];
    const float* lsg  = (const float*)d_in[12];
    const float* lsb  = (const float*)d_in[13];
    const float* lfg  = (const float*)d_in[14];
    const float* lfb  = (const float*)d_in[15];
    const float* W1   = (const float*)d_in[16];
    const float* b1   = (const float*)d_in[17];
    const float* W2   = (const float*)d_in[18];
    const float* b2   = (const float*)d_in[19];

    float* out = (float*)d_out;
    float* slots = out;                       // [B,36,36]; attn slabs follow

    cudaFuncSetAttribute(k_g, cudaFuncAttributeMaxDynamicSharedMemorySize, KG_SMEM);
    cudaFuncSetAttribute(k_projW, cudaFuncAttributeMaxDynamicSharedMemorySize, KP_SMEM);

    k_prep<<<(G3 * ND + 255) / 256, 256>>>(Wih);
    k_gk<<<NB * NL, 128>>>(kn, bih);
    k_w<<<NB, 256>>>(pano, 0, lsg, lsb, Wq, Wk);

    for (int it = 0; it < 3; it++) {
        float* attnT = out + NB * NL * NV * (1 + it);
        const float* sp = it ? (const float*)slots : pano;
        int bs = it ? 1296 : 0;
        if (it == 0) {
            k_cd<<<dim3(NV, NB), 128>>>(ctx, attnT);
            k_projW<<<dim3(NB, 4), 512, KP_SMEM>>>();
        } else {
            k_d2<<<dim3(NL, NB), 128>>>(ctx, attnT);
        }
        k_g<<<dim3(NB, 2), 512, KG_SMEM>>>(attnT, sp, bs, Whh, bhh, lfg, lfb,
                                           W1, b1, W2, b2, it == 0 ? 1 : 0,
                                           attnT, slots);
        if (it < 2)
            k_w<<<NB, 256>>>(slots, 1296, lsg, lsb, Wq, Wk);
    }
}